// round 7
// baseline (speedup 1.0000x reference)
#include <cuda_runtime.h>
#include <math.h>
#include <stdint.h>

// Problem constants
#define NB 256        // batch B
#define NN 1024       // N
#define NK 64         // K
#define INV_TEMP 5.0f // 1/0.2
#define LN_EPS 1e-5f

// Scratch (static device globals; allocation inside kernel_launch is forbidden)
static __device__ float g_S[NN * NN];                    // sinkhorn(A_logits)   4 MB
static __device__ float g_W[NN * NK * NK];               // per-block sinkhorn  16 MB
static __device__ float g_XL[(size_t)NB * NN * NK];      // x_local [b][n][k]   64 MB
static __device__ float g_YT[(size_t)NB * NK * NN];      // normalized [b*K+k][n] 64 MB

// ---------------------------------------------------------------------------
// Kernel 1: row pass of log_sinkhorn on A_logits.
// la = logits/T ; la -= logsumexp(la, axis=-1) ; store to g_S.
// One block per row, 256 threads, 4 elements/thread.
// ---------------------------------------------------------------------------
__global__ void k_sink_row(const float* __restrict__ logits) {
    const int row = blockIdx.x;
    const int t = threadIdx.x;
    const float* rp = logits + (size_t)row * NN;
    float v[4];
    float m = -1e30f;
#pragma unroll
    for (int q = 0; q < 4; ++q) {
        v[q] = rp[t + 256 * q] * INV_TEMP;
        m = fmaxf(m, v[q]);
    }
    __shared__ float red[256];
    red[t] = m;
    __syncthreads();
    for (int s = 128; s > 0; s >>= 1) {
        if (t < s) red[t] = fmaxf(red[t], red[t + s]);
        __syncthreads();
    }
    m = red[0];
    __syncthreads();
    float acc = 0.f;
#pragma unroll
    for (int q = 0; q < 4; ++q) acc += expf(v[q] - m);
    red[t] = acc;
    __syncthreads();
    for (int s = 128; s > 0; s >>= 1) {
        if (t < s) red[t] += red[t + s];
        __syncthreads();
    }
    const float lse = logf(red[0]) + m;
    float* op = g_S + (size_t)row * NN;
#pragma unroll
    for (int q = 0; q < 4; ++q) op[t + 256 * q] = v[q] - lse;
}

// ---------------------------------------------------------------------------
// Kernel 2: column pass + exp. Each block owns 32 columns; 8-way row
// parallelism per column with online logsumexp, then in-place exp.
// ---------------------------------------------------------------------------
__global__ void k_sink_col() {
    const int c0 = blockIdx.x * 32;
    const int t = threadIdx.x;
    const int c = t & 31;
    const int ry = t >> 5;  // 0..7
    float m = -1e30f, s = 0.f;
    for (int i = ry; i < NN; i += 8) {
        float v = g_S[(size_t)i * NN + c0 + c];
        float mn = fmaxf(m, v);
        s = s * expf(m - mn) + expf(v - mn);
        m = mn;
    }
    __shared__ float sm[8][32];
    __shared__ float ss[8][32];
    __shared__ float cl[32];
    sm[ry][c] = m;
    ss[ry][c] = s;
    __syncthreads();
    if (t < 32) {
        float M = -1e30f;
#pragma unroll
        for (int q = 0; q < 8; ++q) M = fmaxf(M, sm[q][t]);
        float S = 0.f;
#pragma unroll
        for (int q = 0; q < 8; ++q) S += ss[q][t] * expf(sm[q][t] - M);
        cl[t] = logf(S) + M;
    }
    __syncthreads();
    const float myl = cl[c];
    for (int i = ry; i < NN; i += 8) {
        size_t idx = (size_t)i * NN + c0 + c;
        g_S[idx] = expf(g_S[idx] - myl);
    }
}

// ---------------------------------------------------------------------------
// Kernel 3: W[t] = log_sinkhorn( (W1[t,:] . W_V) / T ) for each t.
// One block per t; 64x64 logits live in smem; row LSE then column LSE.
// ---------------------------------------------------------------------------
__global__ void k_wsink(const float* __restrict__ W1, const float* __restrict__ WV) {
    const int n = blockIdx.x;
    const int t = threadIdx.x;
    __shared__ float L[64][65];
    __shared__ float w1[8];
    __shared__ float rl[64];
    __shared__ float cl[64];
    if (t < 8) w1[t] = W1[n * 8 + t];
    __syncthreads();
#pragma unroll
    for (int q = 0; q < 16; ++q) {
        int idx = t + 256 * q;
        float acc = 0.f;
#pragma unroll
        for (int k = 0; k < 8; ++k) acc += w1[k] * WV[k * 4096 + idx];
        L[idx >> 6][idx & 63] = acc * INV_TEMP;
    }
    __syncthreads();
    if (t < 64) {  // row logsumexp (over last axis e)
        float m = -1e30f;
        for (int e = 0; e < 64; ++e) m = fmaxf(m, L[t][e]);
        float s = 0.f;
        for (int e = 0; e < 64; ++e) s += expf(L[t][e] - m);
        rl[t] = logf(s) + m;
    }
    __syncthreads();
#pragma unroll
    for (int q = 0; q < 16; ++q) {
        int idx = t + 256 * q;
        L[idx >> 6][idx & 63] -= rl[idx >> 6];
    }
    __syncthreads();
    if (t < 64) {  // column logsumexp (over axis d)
        float m = -1e30f;
        for (int d = 0; d < 64; ++d) m = fmaxf(m, L[d][t]);
        float s = 0.f;
        for (int d = 0; d < 64; ++d) s += expf(L[d][t] - m);
        cl[t] = logf(s) + m;
    }
    __syncthreads();
    float* wp = g_W + (size_t)n * 4096;
#pragma unroll
    for (int q = 0; q < 16; ++q) {
        int idx = t + 256 * q;
        wp[idx] = expf(L[idx >> 6][idx & 63] - cl[idx & 63]);
    }
}

// ---------------------------------------------------------------------------
// Kernel 4: x_local[b,n,o] = sum_i x[b,n,i] * W[n,i,o].
// Block: one n, 64 batch rows. 16x16 threads, 4x4 microtile. Output stored
// [b][n][k] (coalesced float4 writes).
// ---------------------------------------------------------------------------
__global__ void k_xlocal(const float* __restrict__ x) {
    const int n = blockIdx.x;
    const int b0 = blockIdx.y * 64;
    const int t = threadIdx.x;
    __shared__ float Xs[64][68];
    __shared__ float Ws[64][68];
#pragma unroll
    for (int q = 0; q < 4; ++q) {
        int f4 = t + 256 * q;      // 0..1023
        int row = f4 >> 4;
        int ch = (f4 & 15) << 2;
        float4 vx = *(const float4*)(x + (size_t)(b0 + row) * (NN * NK) + n * NK + ch);
        *(float4*)&Xs[row][ch] = vx;
        float4 vw = *(const float4*)(g_W + (size_t)n * (NK * NK) + row * NK + ch);
        *(float4*)&Ws[row][ch] = vw;
    }
    __syncthreads();
    const int tx = (t & 15) << 2;  // output col o
    const int ty = (t >> 4) << 2;  // output row bb
    float acc[4][4] = {};
#pragma unroll 8
    for (int i = 0; i < 64; ++i) {
        float a[4];
#pragma unroll
        for (int j = 0; j < 4; ++j) a[j] = Xs[ty + j][i];
        float4 bv = *(float4*)&Ws[i][tx];
        float bb[4] = {bv.x, bv.y, bv.z, bv.w};
#pragma unroll
        for (int j = 0; j < 4; ++j)
#pragma unroll
            for (int jj = 0; jj < 4; ++jj)
                acc[j][jj] = fmaf(a[j], bb[jj], acc[j][jj]);
    }
#pragma unroll
    for (int j = 0; j < 4; ++j) {
        float4 o = make_float4(acc[j][0], acc[j][1], acc[j][2], acc[j][3]);
        *(float4*)(g_XL + ((size_t)(b0 + ty + j) * NN + n) * NK + tx) = o;
    }
}

// ---------------------------------------------------------------------------
// Kernel 5: layernorm over n (per (b,k)) + transpose to g_YT[(b*K+k)][n].
// Block: one b, 32 k-columns. Pass 1: coalesced stats. Pass 2: 32x32 smem
// tile transpose so writes are n-contiguous.
// ---------------------------------------------------------------------------
__global__ void k_lnt(const float* __restrict__ gamma2, const float* __restrict__ beta2) {
    const int b = blockIdx.x;
    const int k0 = blockIdx.y * 32;
    const int t = threadIdx.x;
    const int kc = t & 31;
    const int nr = t >> 5;  // 0..7
    const float* base = g_XL + (size_t)b * NN * NK;
    float s = 0.f, s2 = 0.f;
    for (int n = nr; n < NN; n += 8) {
        float v = base[(size_t)n * NK + k0 + kc];
        s += v;
        s2 += v * v;
    }
    __shared__ float ps[8][32];
    __shared__ float ps2[8][32];
    ps[nr][kc] = s;
    ps2[nr][kc] = s2;
    __syncthreads();
    __shared__ float mu[32];
    __shared__ float rstd_s[32];
    if (t < 32) {
        float S = 0.f, S2 = 0.f;
#pragma unroll
        for (int q = 0; q < 8; ++q) { S += ps[q][t]; S2 += ps2[q][t]; }
        float m = S * (1.0f / NN);
        float var = S2 * (1.0f / NN) - m * m;
        mu[t] = m;
        rstd_s[t] = rsqrtf(var + LN_EPS);
    }
    __syncthreads();
    __shared__ float T[32][33];
    for (int nt = 0; nt < NN; nt += 32) {
#pragma unroll
        for (int p = 0; p < 4; ++p) {
            int nl = nr + 8 * p;
            T[nl][kc] = base[(size_t)(nt + nl) * NK + k0 + kc];
        }
        __syncthreads();
#pragma unroll
        for (int p = 0; p < 4; ++p) {
            int kl = nr + 8 * p;
            int n = nt + kc;
            float v = (T[kc][kl] - mu[kl]) * rstd_s[kl];
            v = v * gamma2[n] + beta2[n];
            g_YT[(size_t)(b * NK + k0 + kl) * NN + n] = v;
        }
        __syncthreads();
    }
}

// ---------------------------------------------------------------------------
// Kernel 6: big GEMM, transposed formulation.
//   C[nIdx][r] = sum_m g_S[m][nIdx] * g_YT[r][m],  r = b*64 + k
//   out[b*65536 + nIdx*64 + k] = C[nIdx][r]
// 128x128x16 tile, 256 threads, 8x8 microtile, double-buffered smem.
// All LDG/STG are coalesced float4.
// ---------------------------------------------------------------------------
__global__ void __launch_bounds__(256) k_gemm(float* __restrict__ out) {
    const int br = blockIdx.x;  // r tile (0..127)
    const int bn = blockIdx.y;  // n tile (0..7)
    const int t = threadIdx.x;
    __shared__ float As[2][16][128];
    __shared__ float Bs[2][16][132];
    const int n0 = bn * 128;
    const int r0 = br * 128;

    const int am = t >> 5;            // As rows am, am+8
    const int an = (t & 31) << 2;     // As col chunk
    const int brw = t >> 2;           // Bs source rows brw, brw+64
    const int bq = (t & 3) << 2;      // m chunk within a Y row

    float4 la0, la1, lb0, lb1;
    la0 = *(const float4*)(g_S + (size_t)am * NN + n0 + an);
    la1 = *(const float4*)(g_S + (size_t)(am + 8) * NN + n0 + an);
    lb0 = *(const float4*)(g_YT + (size_t)(r0 + brw) * NN + bq);
    lb1 = *(const float4*)(g_YT + (size_t)(r0 + brw + 64) * NN + bq);
    *(float4*)&As[0][am][an] = la0;
    *(float4*)&As[0][am + 8][an] = la1;
    Bs[0][bq + 0][brw] = lb0.x; Bs[0][bq + 1][brw] = lb0.y;
    Bs[0][bq + 2][brw] = lb0.z; Bs[0][bq + 3][brw] = lb0.w;
    Bs[0][bq + 0][brw + 64] = lb1.x; Bs[0][bq + 1][brw + 64] = lb1.y;
    Bs[0][bq + 2][brw + 64] = lb1.z; Bs[0][bq + 3][brw + 64] = lb1.w;
    __syncthreads();

    const int tx = (t & 15) << 2;  // r micro base
    const int ty = (t >> 4) << 2;  // n micro base
    float acc[8][8] = {};
    int cur = 0;
#pragma unroll 1
    for (int it = 0; it < 64; ++it) {
        if (it < 63) {
            const int m0 = (it + 1) * 16;
            la0 = *(const float4*)(g_S + (size_t)(m0 + am) * NN + n0 + an);
            la1 = *(const float4*)(g_S + (size_t)(m0 + am + 8) * NN + n0 + an);
            lb0 = *(const float4*)(g_YT + (size_t)(r0 + brw) * NN + m0 + bq);
            lb1 = *(const float4*)(g_YT + (size_t)(r0 + brw + 64) * NN + m0 + bq);
        }
#pragma unroll
        for (int kk = 0; kk < 16; ++kk) {
            float ar[8], bv[8];
            *(float4*)(ar)     = *(float4*)&As[cur][kk][ty];
            *(float4*)(ar + 4) = *(float4*)&As[cur][kk][ty + 64];
            *(float4*)(bv)     = *(float4*)&Bs[cur][kk][tx];
            *(float4*)(bv + 4) = *(float4*)&Bs[cur][kk][tx + 64];
#pragma unroll
            for (int i = 0; i < 8; ++i)
#pragma unroll
                for (int j = 0; j < 8; ++j)
                    acc[i][j] = fmaf(ar[i], bv[j], acc[i][j]);
        }
        if (it < 63) {
            const int nxt = cur ^ 1;
            *(float4*)&As[nxt][am][an] = la0;
            *(float4*)&As[nxt][am + 8][an] = la1;
            Bs[nxt][bq + 0][brw] = lb0.x; Bs[nxt][bq + 1][brw] = lb0.y;
            Bs[nxt][bq + 2][brw] = lb0.z; Bs[nxt][bq + 3][brw] = lb0.w;
            Bs[nxt][bq + 0][brw + 64] = lb1.x; Bs[nxt][bq + 1][brw + 64] = lb1.y;
            Bs[nxt][bq + 2][brw + 64] = lb1.z; Bs[nxt][bq + 3][brw + 64] = lb1.w;
            __syncthreads();
            cur = nxt;
        }
    }

    // Epilogue: out[b*65536 + n*64 + k], fully coalesced float4.
#pragma unroll
    for (int i = 0; i < 8; ++i) {
        const int nIdx = n0 + ((i < 4) ? (ty + i) : (ty + 64 + i - 4));
#pragma unroll
        for (int jh = 0; jh < 2; ++jh) {
            const int rBase = r0 + jh * 64 + tx;  // (rBase & 63) == tx
            float4 o = make_float4(acc[i][jh * 4 + 0], acc[i][jh * 4 + 1],
                                   acc[i][jh * 4 + 2], acc[i][jh * 4 + 3]);
            *(float4*)(out + (size_t)(rBase >> 6) * (NN * NK) + (size_t)nIdx * NK + tx) = o;
        }
    }
}

// ---------------------------------------------------------------------------
extern "C" void kernel_launch(void* const* d_in, const int* in_sizes, int n_in,
                              void* d_out, int out_size) {
    (void)in_sizes; (void)n_in; (void)out_size;
    const float* x        = (const float*)d_in[0];  // [B, N*K]
    const float* A_logits = (const float*)d_in[1];  // [N, N]
    const float* W1       = (const float*)d_in[2];  // [N, 8]
    const float* WV       = (const float*)d_in[3];  // [8, K, K]
    const float* gamma2   = (const float*)d_in[4];  // [N]
    const float* beta2    = (const float*)d_in[5];  // [N]
    float* out = (float*)d_out;

    k_sink_row<<<NN, 256>>>(A_logits);
    k_sink_col<<<NN / 32, 256>>>();
    k_wsink<<<NN, 256>>>(W1, WV);
    k_xlocal<<<dim3(NN, NB / 64), 256>>>(x);
    k_lnt<<<dim3(NB, 2), 256>>>(gamma2, beta2);
    k_gemm<<<dim3(128, 8), 256>>>(out);
}

// round 9
// speedup vs baseline: 1.8303x; 1.8303x over previous
#include <cuda_runtime.h>
#include <cuda_bf16.h>
#include <math.h>
#include <stdint.h>

// Problem constants
#define NB 256        // batch B
#define NN 1024       // N
#define NK 64         // K
#define INV_TEMP 5.0f // 1/0.2
#define LN_EPS 1e-5f

// Scratch (static device globals; allocation inside kernel_launch is forbidden)
static __device__ float g_S[NN * NN];                         // sinkhorn(A_logits) 4 MB
static __device__ float g_W[NN * NK * NK];                    // per-block sinkhorn 16 MB
static __device__ float g_XL[(size_t)NB * NN * NK];           // x_local [b][n][k] 64 MB
static __device__ __nv_bfloat16 g_Yhi[(size_t)NB * NK * NN];  // Y hi [r][m] 32 MB
static __device__ __nv_bfloat16 g_Ylo[(size_t)NB * NK * NN];  // Y lo [r][m] 32 MB
static __device__ __nv_bfloat16 g_SThi[NN * NN];              // (S-c)^T hi [n][m] 2 MB
static __device__ __nv_bfloat16 g_STlo[NN * NN];              // (S-c)^T lo [n][m] 2 MB
static __device__ float g_c[NN];                              // column means of S
static __device__ float g_SY[NB * NK];                        // per-row sums of Y

// ============================ PTX helpers (sm_80-era only!) ============================
__device__ __forceinline__ uint32_t smem_u32(const void* p) {
    uint32_t a;
    asm("{ .reg .u64 t; cvta.to.shared.u64 t, %1; cvt.u32.u64 %0, t; }" : "=r"(a) : "l"(p));
    return a;
}
__device__ __forceinline__ void cpa16(uint32_t s, const void* g) {
    asm volatile("cp.async.cg.shared.global [%0], [%1], 16;" :: "r"(s), "l"(g));
}
__device__ __forceinline__ void ldm4(uint32_t* r, uint32_t a) {
    asm volatile("ldmatrix.sync.aligned.m8n8.x4.shared.b16 {%0,%1,%2,%3}, [%4];"
                 : "=r"(r[0]), "=r"(r[1]), "=r"(r[2]), "=r"(r[3]) : "r"(a));
}
__device__ __forceinline__ void mma_bf16(float* d, const uint32_t* a, const uint32_t* b) {
    asm volatile(
        "mma.sync.aligned.m16n8k16.row.col.f32.bf16.bf16.f32 "
        "{%0,%1,%2,%3}, {%4,%5,%6,%7}, {%8,%9}, {%0,%1,%2,%3};"
        : "+f"(d[0]), "+f"(d[1]), "+f"(d[2]), "+f"(d[3])
        : "r"(a[0]), "r"(a[1]), "r"(a[2]), "r"(a[3]), "r"(b[0]), "r"(b[1]));
}

// ---------------------------------------------------------------------------
// Kernel 1: row pass of log_sinkhorn on A_logits.
// ---------------------------------------------------------------------------
__global__ void k_sink_row(const float* __restrict__ logits) {
    const int row = blockIdx.x;
    const int t = threadIdx.x;
    const float* rp = logits + (size_t)row * NN;
    float v[4];
    float m = -1e30f;
#pragma unroll
    for (int q = 0; q < 4; ++q) {
        v[q] = rp[t + 256 * q] * INV_TEMP;
        m = fmaxf(m, v[q]);
    }
    __shared__ float red[256];
    red[t] = m;
    __syncthreads();
    for (int s = 128; s > 0; s >>= 1) {
        if (t < s) red[t] = fmaxf(red[t], red[t + s]);
        __syncthreads();
    }
    m = red[0];
    __syncthreads();
    float acc = 0.f;
#pragma unroll
    for (int q = 0; q < 4; ++q) acc += expf(v[q] - m);
    red[t] = acc;
    __syncthreads();
    for (int s = 128; s > 0; s >>= 1) {
        if (t < s) red[t] += red[t + s];
        __syncthreads();
    }
    const float lse = logf(red[0]) + m;
    float* op = g_S + (size_t)row * NN;
#pragma unroll
    for (int q = 0; q < 4; ++q) op[t + 256 * q] = v[q] - lse;
}

// ---------------------------------------------------------------------------
// Kernel 2: column pass + exp + column means into g_c.
// ---------------------------------------------------------------------------
__global__ void k_sink_col() {
    const int c0 = blockIdx.x * 32;
    const int t = threadIdx.x;
    const int c = t & 31;
    const int ry = t >> 5;  // 0..7
    float m = -1e30f, s = 0.f;
    for (int i = ry; i < NN; i += 8) {
        float v = g_S[(size_t)i * NN + c0 + c];
        float mn = fmaxf(m, v);
        s = s * expf(m - mn) + expf(v - mn);
        m = mn;
    }
    __shared__ float sm[8][32];
    __shared__ float ss[8][32];
    __shared__ float cl[32];
    sm[ry][c] = m;
    ss[ry][c] = s;
    __syncthreads();
    if (t < 32) {
        float M = -1e30f;
#pragma unroll
        for (int q = 0; q < 8; ++q) M = fmaxf(M, sm[q][t]);
        float S = 0.f;
#pragma unroll
        for (int q = 0; q < 8; ++q) S += ss[q][t] * expf(sm[q][t] - M);
        cl[t] = logf(S) + M;
    }
    __syncthreads();
    const float myl = cl[c];
    float csum = 0.f;
    for (int i = ry; i < NN; i += 8) {
        size_t idx = (size_t)i * NN + c0 + c;
        float e = expf(g_S[idx] - myl);
        g_S[idx] = e;
        csum += e;
    }
    __syncthreads();
    ss[ry][c] = csum;
    __syncthreads();
    if (t < 32) {
        float S = 0.f;
#pragma unroll
        for (int q = 0; q < 8; ++q) S += ss[q][t];
        g_c[c0 + t] = S * (1.0f / NN);
    }
}

// ---------------------------------------------------------------------------
// Kernel 2b: ST'[n][m] = S[m][n] - c[n], split into bf16 hi/lo.
// ---------------------------------------------------------------------------
__global__ void k_strans() {
    const int m0 = blockIdx.x * 32, n0 = blockIdx.y * 32;
    const int t = threadIdx.x;
    const int j = t & 31, i0 = t >> 5;
    __shared__ float T[32][33];
#pragma unroll
    for (int p = 0; p < 4; ++p)
        T[i0 + 8 * p][j] = g_S[(size_t)(m0 + i0 + 8 * p) * NN + n0 + j];
    __syncthreads();
#pragma unroll
    for (int p = 0; p < 4; ++p) {
        int nl = i0 + 8 * p;
        float v = T[j][nl] - g_c[n0 + nl];
        __nv_bfloat16 hi = __float2bfloat16(v);
        size_t idx = (size_t)(n0 + nl) * NN + m0 + j;
        g_SThi[idx] = hi;
        g_STlo[idx] = __float2bfloat16(v - __bfloat162float(hi));
    }
}

// ---------------------------------------------------------------------------
// Kernel 3: W[t] = log_sinkhorn( (W1[t,:] . W_V) / T ) for each t.
// ---------------------------------------------------------------------------
__global__ void k_wsink(const float* __restrict__ W1, const float* __restrict__ WV) {
    const int n = blockIdx.x;
    const int t = threadIdx.x;
    __shared__ float L[64][65];
    __shared__ float w1[8];
    __shared__ float rl[64];
    __shared__ float cl[64];
    if (t < 8) w1[t] = W1[n * 8 + t];
    __syncthreads();
#pragma unroll
    for (int q = 0; q < 16; ++q) {
        int idx = t + 256 * q;
        float acc = 0.f;
#pragma unroll
        for (int k = 0; k < 8; ++k) acc += w1[k] * WV[k * 4096 + idx];
        L[idx >> 6][idx & 63] = acc * INV_TEMP;
    }
    __syncthreads();
    if (t < 64) {
        float m = -1e30f;
        for (int e = 0; e < 64; ++e) m = fmaxf(m, L[t][e]);
        float s = 0.f;
        for (int e = 0; e < 64; ++e) s += expf(L[t][e] - m);
        rl[t] = logf(s) + m;
    }
    __syncthreads();
#pragma unroll
    for (int q = 0; q < 16; ++q) {
        int idx = t + 256 * q;
        L[idx >> 6][idx & 63] -= rl[idx >> 6];
    }
    __syncthreads();
    if (t < 64) {
        float m = -1e30f;
        for (int d = 0; d < 64; ++d) m = fmaxf(m, L[d][t]);
        float s = 0.f;
        for (int d = 0; d < 64; ++d) s += expf(L[d][t] - m);
        cl[t] = logf(s) + m;
    }
    __syncthreads();
    float* wp = g_W + (size_t)n * 4096;
#pragma unroll
    for (int q = 0; q < 16; ++q) {
        int idx = t + 256 * q;
        wp[idx] = expf(L[idx >> 6][idx & 63] - cl[idx & 63]);
    }
}

// ---------------------------------------------------------------------------
// Kernel 4: x_local[b,n,o] = sum_i x[b,n,i] * W[n,i,o].  (kept fp32: its
// output feeds layernorm whose tiny post-cancellation signal cannot survive
// bf16 quantization of x_local itself)
// ---------------------------------------------------------------------------
__global__ void k_xlocal(const float* __restrict__ x) {
    const int n = blockIdx.x;
    const int b0 = blockIdx.y * 64;
    const int t = threadIdx.x;
    __shared__ float Xs[64][68];
    __shared__ float Ws[64][68];
#pragma unroll
    for (int q = 0; q < 4; ++q) {
        int f4 = t + 256 * q;
        int row = f4 >> 4;
        int ch = (f4 & 15) << 2;
        float4 vx = *(const float4*)(x + (size_t)(b0 + row) * (NN * NK) + n * NK + ch);
        *(float4*)&Xs[row][ch] = vx;
        float4 vw = *(const float4*)(g_W + (size_t)n * (NK * NK) + row * NK + ch);
        *(float4*)&Ws[row][ch] = vw;
    }
    __syncthreads();
    const int tx = (t & 15) << 2;
    const int ty = (t >> 4) << 2;
    float acc[4][4] = {};
#pragma unroll 8
    for (int i = 0; i < 64; ++i) {
        float a[4];
#pragma unroll
        for (int j = 0; j < 4; ++j) a[j] = Xs[ty + j][i];
        float4 bv = *(float4*)&Ws[i][tx];
        float bb[4] = {bv.x, bv.y, bv.z, bv.w};
#pragma unroll
        for (int j = 0; j < 4; ++j)
#pragma unroll
            for (int jj = 0; jj < 4; ++jj)
                acc[j][jj] = fmaf(a[j], bb[jj], acc[j][jj]);
    }
#pragma unroll
    for (int j = 0; j < 4; ++j) {
        float4 o = make_float4(acc[j][0], acc[j][1], acc[j][2], acc[j][3]);
        *(float4*)(g_XL + ((size_t)(b0 + ty + j) * NN + n) * NK + tx) = o;
    }
}

// ---------------------------------------------------------------------------
// Kernel 5: layernorm over n (per (b,k)) + transpose; emits bf16 hi/lo split
// of Y into g_Yhi/g_Ylo [r][m] and exact fp32 row sums S_Y into g_SY.
// ---------------------------------------------------------------------------
__global__ void k_lnt(const float* __restrict__ gamma2, const float* __restrict__ beta2) {
    const int b = blockIdx.x;
    const int k0 = blockIdx.y * 32;
    const int t = threadIdx.x;
    const int kc = t & 31;
    const int nr = t >> 5;  // 0..7
    const float* base = g_XL + (size_t)b * NN * NK;
    float s = 0.f, s2 = 0.f;
    for (int n = nr; n < NN; n += 8) {
        float v = base[(size_t)n * NK + k0 + kc];
        s += v;
        s2 += v * v;
    }
    __shared__ float ps[8][32];
    __shared__ float ps2[8][32];
    ps[nr][kc] = s;
    ps2[nr][kc] = s2;
    __syncthreads();
    __shared__ float mu[32];
    __shared__ float rstd_s[32];
    if (t < 32) {
        float S = 0.f, S2 = 0.f;
#pragma unroll
        for (int q = 0; q < 8; ++q) { S += ps[q][t]; S2 += ps2[q][t]; }
        float m = S * (1.0f / NN);
        float var = S2 * (1.0f / NN) - m * m;
        mu[t] = m;
        rstd_s[t] = rsqrtf(var + LN_EPS);
    }
    __syncthreads();
    __shared__ float T[32][33];
    float accS[4] = {0.f, 0.f, 0.f, 0.f};
    for (int nt = 0; nt < NN; nt += 32) {
#pragma unroll
        for (int p = 0; p < 4; ++p) {
            int nl = nr + 8 * p;
            T[nl][kc] = base[(size_t)(nt + nl) * NK + k0 + kc];
        }
        __syncthreads();
#pragma unroll
        for (int p = 0; p < 4; ++p) {
            int kl = nr + 8 * p;
            int n = nt + kc;
            float v = (T[kc][kl] - mu[kl]) * rstd_s[kl];
            v = v * gamma2[n] + beta2[n];
            accS[p] += v;
            __nv_bfloat16 hi = __float2bfloat16(v);
            size_t idx = (size_t)(b * NK + k0 + kl) * NN + n;
            g_Yhi[idx] = hi;
            g_Ylo[idx] = __float2bfloat16(v - __bfloat162float(hi));
        }
        __syncthreads();
    }
#pragma unroll
    for (int p = 0; p < 4; ++p) {
        float v = accS[p];
#pragma unroll
        for (int off = 16; off; off >>= 1) v += __shfl_xor_sync(0xffffffffu, v, off);
        if (kc == 0) g_SY[b * NK + k0 + nr + 8 * p] = v;
    }
}

// ---------------------------------------------------------------------------
// Kernel 6: tensor-core GEMM via mma.sync (bf16, fp32 accum), 3 hi/lo passes
// on mean-subtracted A'.  D[r][n] = sum_m Y[r][m] * ST[n][m]; out = D + c*SY.
// CTA tile 128x128, K-chunk 64, double-buffered cp.async (144 KB smem).
// 8 warps, warp tile 32x64, ldmatrix fragments reused across the 3 passes.
// ---------------------------------------------------------------------------
#define T_ROWB 144                 // smem bytes per tile row (72 bf16) — LDSM conflict-free
#define TILE_B (128 * T_ROWB)      // 18432
#define STAGE_B (4 * TILE_B)       // 73728
#define OFF_YHI 0u
#define OFF_YLO ((uint32_t)TILE_B)
#define OFF_SHI ((uint32_t)(2 * TILE_B))
#define OFF_SLO ((uint32_t)(3 * TILE_B))

__device__ __forceinline__ void g_load_stage(uint32_t st, int r0, int n0, int m0, int t) {
    for (int i = t; i < 1024; i += 256) {
        const int row = i >> 3, q = i & 7;
        const uint32_t so = (uint32_t)(row * T_ROWB + q * 16);
        const size_t yo = (size_t)(r0 + row) * NN + m0 + q * 8;
        const size_t so2 = (size_t)(n0 + row) * NN + m0 + q * 8;
        cpa16(st + OFF_YHI + so, g_Yhi + yo);
        cpa16(st + OFF_YLO + so, g_Ylo + yo);
        cpa16(st + OFF_SHI + so, g_SThi + so2);
        cpa16(st + OFF_SLO + so, g_STlo + so2);
    }
}

__global__ void __launch_bounds__(256, 1) k_gemm_mma(float* __restrict__ out) {
    extern __shared__ char dsm[];
    const int t = threadIdx.x;
    const int r0 = blockIdx.x * 128;
    const int n0 = blockIdx.y * 128;
    __shared__ float s_c[128], s_sy[128];
    if (t < 128) { s_c[t] = g_c[n0 + t]; s_sy[t] = g_SY[r0 + t]; }
    const uint32_t sb = smem_u32(dsm);

    // Preload chunks 0,1 as two cp.async groups
    g_load_stage(sb, r0, n0, 0, t);
    asm volatile("cp.async.commit_group;" ::: "memory");
    g_load_stage(sb + STAGE_B, r0, n0, 64, t);
    asm volatile("cp.async.commit_group;" ::: "memory");

    const int L = t & 31, w = t >> 5;
    const int wr = (w >> 1) * 32;  // warp r base 0..96
    const int wn = (w & 1) * 64;   // warp n base 0/64
    // ldmatrix lane addressing (byte offsets within a tile)
    const uint32_t a_l = (uint32_t)((wr + (L & 15)) * T_ROWB + ((L >> 4) * 8) * 2);
    const uint32_t b_l = (uint32_t)((wn + (L & 7) + ((L & 16) ? 8 : 0)) * T_ROWB + ((L & 8) ? 16 : 0));

    float acc[2][8][4] = {};

#pragma unroll 1
    for (int c = 0; c < 16; ++c) {
        if (c == 15) asm volatile("cp.async.wait_group 0;" ::: "memory");
        else         asm volatile("cp.async.wait_group 1;" ::: "memory");
        __syncthreads();
        const uint32_t st = sb + (uint32_t)(c & 1) * STAGE_B;
#pragma unroll
        for (int ks = 0; ks < 4; ++ks) {
            uint32_t ah[2][4], al[2][4], bh[4][4], bl[4][4];
            const uint32_t ka = st + a_l + ks * 32;
            const uint32_t kb = st + b_l + ks * 32;
#pragma unroll
            for (int mt = 0; mt < 2; ++mt) {
                ldm4(ah[mt], ka + OFF_YHI + mt * (16 * T_ROWB));
                ldm4(al[mt], ka + OFF_YLO + mt * (16 * T_ROWB));
            }
#pragma unroll
            for (int bj = 0; bj < 4; ++bj) {
                ldm4(bh[bj], kb + OFF_SHI + bj * (16 * T_ROWB));
                ldm4(bl[bj], kb + OFF_SLO + bj * (16 * T_ROWB));
            }
#pragma unroll
            for (int mt = 0; mt < 2; ++mt)
#pragma unroll
                for (int nj = 0; nj < 8; ++nj) {
                    const uint32_t* BH = &bh[nj >> 1][(nj & 1) * 2];
                    const uint32_t* BL = &bl[nj >> 1][(nj & 1) * 2];
                    mma_bf16(acc[mt][nj], ah[mt], BH);  // hi*hi
                    mma_bf16(acc[mt][nj], ah[mt], BL);  // hi*lo
                    mma_bf16(acc[mt][nj], al[mt], BH);  // lo*hi
                }
        }
        __syncthreads();
        if (c + 2 < 16) {
            g_load_stage(st, r0, n0, (c + 2) * 64, t);
            asm volatile("cp.async.commit_group;" ::: "memory");
        }
    }

    // Epilogue: acc -> smem [n][r] (conflict-free), then coalesced float4 STG.
    float* so = (float*)dsm;
#pragma unroll
    for (int mt = 0; mt < 2; ++mt)
#pragma unroll
        for (int nj = 0; nj < 8; ++nj) {
            const int rl = wr + mt * 16 + (L >> 2);
            const int nl = wn + nj * 8 + (L & 3) * 2;
            so[nl * 132 + rl]           = acc[mt][nj][0];
            so[(nl + 1) * 132 + rl]     = acc[mt][nj][1];
            so[nl * 132 + rl + 8]       = acc[mt][nj][2];
            so[(nl + 1) * 132 + rl + 8] = acc[mt][nj][3];
        }
    __syncthreads();
    for (int i = t; i < 4096; i += 256) {
        const int n = i >> 5;
        const int rq = (i & 31) * 4;
        const float cn = s_c[n];
        float4 v;
        v.x = so[n * 132 + rq]     + cn * s_sy[rq];
        v.y = so[n * 132 + rq + 1] + cn * s_sy[rq + 1];
        v.z = so[n * 132 + rq + 2] + cn * s_sy[rq + 2];
        v.w = so[n * 132 + rq + 3] + cn * s_sy[rq + 3];
        const int r = r0 + rq;
        *(float4*)(out + (size_t)(r >> 6) * (NN * NK) + (size_t)(n0 + n) * NK + (r & 63)) = v;
    }
}

// ---------------------------------------------------------------------------
extern "C" void kernel_launch(void* const* d_in, const int* in_sizes, int n_in,
                              void* d_out, int out_size) {
    (void)in_sizes; (void)n_in; (void)out_size;
    const float* x        = (const float*)d_in[0];  // [B, N*K]
    const float* A_logits = (const float*)d_in[1];  // [N, N]
    const float* W1       = (const float*)d_in[2];  // [N, 8]
    const float* WV       = (const float*)d_in[3];  // [8, K, K]
    const float* gamma2   = (const float*)d_in[4];  // [N]
    const float* beta2    = (const float*)d_in[5];  // [N]
    float* out = (float*)d_out;

    static int smem_set = 0;
    if (!smem_set) {
        cudaFuncSetAttribute(k_gemm_mma, cudaFuncAttributeMaxDynamicSharedMemorySize,
                             2 * STAGE_B);
        smem_set = 1;
    }

    k_sink_row<<<NN, 256>>>(A_logits);
    k_sink_col<<<NN / 32, 256>>>();
    k_strans<<<dim3(32, 32), 256>>>();
    k_wsink<<<NN, 256>>>(W1, WV);
    k_xlocal<<<dim3(NN, NB / 64), 256>>>(x);
    k_lnt<<<dim3(NB, 2), 256>>>(gamma2, beta2);
    k_gemm_mma<<<dim3(128, 8), 256, 2 * STAGE_B>>>(out);
}

// round 10
// speedup vs baseline: 3.2757x; 1.7898x over previous
#include <cuda_runtime.h>
#include <cuda_bf16.h>
#include <cuda_fp16.h>
#include <math.h>
#include <stdint.h>

// Problem constants
#define NB 256        // batch B
#define NN 1024       // N
#define NK 64         // K
#define INV_TEMP 5.0f // 1/0.2
#define LN_EPS 1e-5f
#define A_SCALE 4096.0f
#define A_INV_SCALE 2.44140625e-4f

// Scratch (static device globals; allocation inside kernel_launch is forbidden)
static __device__ float g_S[NN * NN];                    // sinkhorn(A_logits) 4 MB
static __device__ float g_W[NN * NK * NK];               // per-block sinkhorn 16 MB
static __device__ float g_XL[(size_t)NB * NN * NK];      // x_local [b][n][k] 64 MB
static __device__ __half g_Yh[(size_t)NB * NK * NN];     // Y fp16 [r][m] 32 MB
static __device__ __half g_STh[NN * NN];                 // (S-c)^T * 4096, fp16 [n][m] 2 MB
static __device__ float g_c[NN];                         // column means of S
static __device__ float g_SY[NB * NK];                   // per-row sums of Y (exact fp32)

// ============================ PTX helpers (sm_80-era only!) ============================
__device__ __forceinline__ uint32_t smem_u32(const void* p) {
    uint32_t a;
    asm("{ .reg .u64 t; cvta.to.shared.u64 t, %1; cvt.u32.u64 %0, t; }" : "=r"(a) : "l"(p));
    return a;
}
__device__ __forceinline__ void cpa16(uint32_t s, const void* g) {
    asm volatile("cp.async.cg.shared.global [%0], [%1], 16;" :: "r"(s), "l"(g));
}
__device__ __forceinline__ void ldm4(uint32_t* r, uint32_t a) {
    asm volatile("ldmatrix.sync.aligned.m8n8.x4.shared.b16 {%0,%1,%2,%3}, [%4];"
                 : "=r"(r[0]), "=r"(r[1]), "=r"(r[2]), "=r"(r[3]) : "r"(a));
}
__device__ __forceinline__ void mma_fp16(float* d, const uint32_t* a, const uint32_t* b) {
    asm volatile(
        "mma.sync.aligned.m16n8k16.row.col.f32.f16.f16.f32 "
        "{%0,%1,%2,%3}, {%4,%5,%6,%7}, {%8,%9}, {%0,%1,%2,%3};"
        : "+f"(d[0]), "+f"(d[1]), "+f"(d[2]), "+f"(d[3])
        : "r"(a[0]), "r"(a[1]), "r"(a[2]), "r"(a[3]), "r"(b[0]), "r"(b[1]));
}

// ---------------------------------------------------------------------------
// Kernel 1: row pass of log_sinkhorn on A_logits.
// ---------------------------------------------------------------------------
__global__ void k_sink_row(const float* __restrict__ logits) {
    const int row = blockIdx.x;
    const int t = threadIdx.x;
    const float* rp = logits + (size_t)row * NN;
    float v[4];
    float m = -1e30f;
#pragma unroll
    for (int q = 0; q < 4; ++q) {
        v[q] = rp[t + 256 * q] * INV_TEMP;
        m = fmaxf(m, v[q]);
    }
    __shared__ float red[256];
    red[t] = m;
    __syncthreads();
    for (int s = 128; s > 0; s >>= 1) {
        if (t < s) red[t] = fmaxf(red[t], red[t + s]);
        __syncthreads();
    }
    m = red[0];
    __syncthreads();
    float acc = 0.f;
#pragma unroll
    for (int q = 0; q < 4; ++q) acc += expf(v[q] - m);
    red[t] = acc;
    __syncthreads();
    for (int s = 128; s > 0; s >>= 1) {
        if (t < s) red[t] += red[t + s];
        __syncthreads();
    }
    const float lse = logf(red[0]) + m;
    float* op = g_S + (size_t)row * NN;
#pragma unroll
    for (int q = 0; q < 4; ++q) op[t + 256 * q] = v[q] - lse;
}

// ---------------------------------------------------------------------------
// Kernel 2: column pass + exp + column means into g_c.
// ---------------------------------------------------------------------------
__global__ void k_sink_col() {
    const int c0 = blockIdx.x * 32;
    const int t = threadIdx.x;
    const int c = t & 31;
    const int ry = t >> 5;  // 0..7
    float m = -1e30f, s = 0.f;
    for (int i = ry; i < NN; i += 8) {
        float v = g_S[(size_t)i * NN + c0 + c];
        float mn = fmaxf(m, v);
        s = s * expf(m - mn) + expf(v - mn);
        m = mn;
    }
    __shared__ float sm[8][32];
    __shared__ float ss[8][32];
    __shared__ float cl[32];
    sm[ry][c] = m;
    ss[ry][c] = s;
    __syncthreads();
    if (t < 32) {
        float M = -1e30f;
#pragma unroll
        for (int q = 0; q < 8; ++q) M = fmaxf(M, sm[q][t]);
        float S = 0.f;
#pragma unroll
        for (int q = 0; q < 8; ++q) S += ss[q][t] * expf(sm[q][t] - M);
        cl[t] = logf(S) + M;
    }
    __syncthreads();
    const float myl = cl[c];
    float csum = 0.f;
    for (int i = ry; i < NN; i += 8) {
        size_t idx = (size_t)i * NN + c0 + c;
        float e = expf(g_S[idx] - myl);
        g_S[idx] = e;
        csum += e;
    }
    __syncthreads();
    ss[ry][c] = csum;
    __syncthreads();
    if (t < 32) {
        float S = 0.f;
#pragma unroll
        for (int q = 0; q < 8; ++q) S += ss[q][t];
        g_c[c0 + t] = S * (1.0f / NN);
    }
}

// ---------------------------------------------------------------------------
// Kernel 2b: STh[n][m] = (S[m][n] - c[n]) * A_SCALE, fp16.
// ---------------------------------------------------------------------------
__global__ void k_strans() {
    const int m0 = blockIdx.x * 32, n0 = blockIdx.y * 32;
    const int t = threadIdx.x;
    const int j = t & 31, i0 = t >> 5;
    __shared__ float T[32][33];
#pragma unroll
    for (int p = 0; p < 4; ++p)
        T[i0 + 8 * p][j] = g_S[(size_t)(m0 + i0 + 8 * p) * NN + n0 + j];
    __syncthreads();
#pragma unroll
    for (int p = 0; p < 4; ++p) {
        int nl = i0 + 8 * p;
        float v = (T[j][nl] - g_c[n0 + nl]) * A_SCALE;
        g_STh[(size_t)(n0 + nl) * NN + m0 + j] = __float2half(v);
    }
}

// ---------------------------------------------------------------------------
// Kernel 3: W[t] = log_sinkhorn( (W1[t,:] . W_V) / T ) for each t.
// ---------------------------------------------------------------------------
__global__ void k_wsink(const float* __restrict__ W1, const float* __restrict__ WV) {
    const int n = blockIdx.x;
    const int t = threadIdx.x;
    __shared__ float L[64][65];
    __shared__ float w1[8];
    __shared__ float rl[64];
    __shared__ float cl[64];
    if (t < 8) w1[t] = W1[n * 8 + t];
    __syncthreads();
#pragma unroll
    for (int q = 0; q < 16; ++q) {
        int idx = t + 256 * q;
        float acc = 0.f;
#pragma unroll
        for (int k = 0; k < 8; ++k) acc += w1[k] * WV[k * 4096 + idx];
        L[idx >> 6][idx & 63] = acc * INV_TEMP;
    }
    __syncthreads();
    if (t < 64) {
        float m = -1e30f;
        for (int e = 0; e < 64; ++e) m = fmaxf(m, L[t][e]);
        float s = 0.f;
        for (int e = 0; e < 64; ++e) s += expf(L[t][e] - m);
        rl[t] = logf(s) + m;
    }
    __syncthreads();
#pragma unroll
    for (int q = 0; q < 16; ++q) {
        int idx = t + 256 * q;
        L[idx >> 6][idx & 63] -= rl[idx >> 6];
    }
    __syncthreads();
    if (t < 64) {
        float m = -1e30f;
        for (int d = 0; d < 64; ++d) m = fmaxf(m, L[d][t]);
        float s = 0.f;
        for (int d = 0; d < 64; ++d) s += expf(L[d][t] - m);
        cl[t] = logf(s) + m;
    }
    __syncthreads();
    float* wp = g_W + (size_t)n * 4096;
#pragma unroll
    for (int q = 0; q < 16; ++q) {
        int idx = t + 256 * q;
        wp[idx] = expf(L[idx >> 6][idx & 63] - cl[idx & 63]);
    }
}

// ---------------------------------------------------------------------------
// Kernel 4: x_local[b,n,o] = sum_i x[b,n,i] * W[n,i,o].  (fp32, unchanged)
// ---------------------------------------------------------------------------
__global__ void k_xlocal(const float* __restrict__ x) {
    const int n = blockIdx.x;
    const int b0 = blockIdx.y * 64;
    const int t = threadIdx.x;
    __shared__ float Xs[64][68];
    __shared__ float Ws[64][68];
#pragma unroll
    for (int q = 0; q < 4; ++q) {
        int f4 = t + 256 * q;
        int row = f4 >> 4;
        int ch = (f4 & 15) << 2;
        float4 vx = *(const float4*)(x + (size_t)(b0 + row) * (NN * NK) + n * NK + ch);
        *(float4*)&Xs[row][ch] = vx;
        float4 vw = *(const float4*)(g_W + (size_t)n * (NK * NK) + row * NK + ch);
        *(float4*)&Ws[row][ch] = vw;
    }
    __syncthreads();
    const int tx = (t & 15) << 2;
    const int ty = (t >> 4) << 2;
    float acc[4][4] = {};
#pragma unroll 8
    for (int i = 0; i < 64; ++i) {
        float a[4];
#pragma unroll
        for (int j = 0; j < 4; ++j) a[j] = Xs[ty + j][i];
        float4 bv = *(float4*)&Ws[i][tx];
        float bb[4] = {bv.x, bv.y, bv.z, bv.w};
#pragma unroll
        for (int j = 0; j < 4; ++j)
#pragma unroll
            for (int jj = 0; jj < 4; ++jj)
                acc[j][jj] = fmaf(a[j], bb[jj], acc[j][jj]);
    }
#pragma unroll
    for (int j = 0; j < 4; ++j) {
        float4 o = make_float4(acc[j][0], acc[j][1], acc[j][2], acc[j][3]);
        *(float4*)(g_XL + ((size_t)(b0 + ty + j) * NN + n) * NK + tx) = o;
    }
}

// ---------------------------------------------------------------------------
// Kernel 5: layernorm over n (per (b,k)) + transpose; emits fp16 Y into
// g_Yh [r][m] and exact fp32 row sums S_Y into g_SY.
// ---------------------------------------------------------------------------
__global__ void k_lnt(const float* __restrict__ gamma2, const float* __restrict__ beta2) {
    const int b = blockIdx.x;
    const int k0 = blockIdx.y * 32;
    const int t = threadIdx.x;
    const int kc = t & 31;
    const int nr = t >> 5;  // 0..7
    const float* base = g_XL + (size_t)b * NN * NK;
    float s = 0.f, s2 = 0.f;
    for (int n = nr; n < NN; n += 8) {
        float v = base[(size_t)n * NK + k0 + kc];
        s += v;
        s2 += v * v;
    }
    __shared__ float ps[8][32];
    __shared__ float ps2[8][32];
    ps[nr][kc] = s;
    ps2[nr][kc] = s2;
    __syncthreads();
    __shared__ float mu[32];
    __shared__ float rstd_s[32];
    if (t < 32) {
        float S = 0.f, S2 = 0.f;
#pragma unroll
        for (int q = 0; q < 8; ++q) { S += ps[q][t]; S2 += ps2[q][t]; }
        float m = S * (1.0f / NN);
        float var = S2 * (1.0f / NN) - m * m;
        mu[t] = m;
        rstd_s[t] = rsqrtf(var + LN_EPS);
    }
    __syncthreads();
    __shared__ float T[32][33];
    float accS[4] = {0.f, 0.f, 0.f, 0.f};
    for (int nt = 0; nt < NN; nt += 32) {
#pragma unroll
        for (int p = 0; p < 4; ++p) {
            int nl = nr + 8 * p;
            T[nl][kc] = base[(size_t)(nt + nl) * NK + k0 + kc];
        }
        __syncthreads();
#pragma unroll
        for (int p = 0; p < 4; ++p) {
            int kl = nr + 8 * p;
            int n = nt + kc;
            float v = (T[kc][kl] - mu[kl]) * rstd_s[kl];
            v = v * gamma2[n] + beta2[n];
            accS[p] += v;
            g_Yh[(size_t)(b * NK + k0 + kl) * NN + n] = __float2half(v);
        }
        __syncthreads();
    }
#pragma unroll
    for (int p = 0; p < 4; ++p) {
        float v = accS[p];
#pragma unroll
        for (int off = 16; off; off >>= 1) v += __shfl_xor_sync(0xffffffffu, v, off);
        if (kc == 0) g_SY[b * NK + k0 + nr + 8 * p] = v;
    }
}

// ---------------------------------------------------------------------------
// Kernel 6: single-pass fp16 tensor-core GEMM on mean-subtracted, scaled A'.
//   D[r][n] = sum_m Yh[r][m] * STh[n][m];  out = D/A_SCALE + c[n]*SY[r].
// CTA tile 128x128, K-chunk 64, double-buffered cp.async (72 KB smem).
// 8 warps, warp tile 32x64.
// ---------------------------------------------------------------------------
#define T_ROWB 144                 // smem bytes per tile row (72 fp16) — LDSM conflict-free
#define TILE_B (128 * T_ROWB)      // 18432
#define STAGE_B (2 * TILE_B)       // 36864
#define OFF_Y 0u
#define OFF_S ((uint32_t)TILE_B)

__device__ __forceinline__ void g_load_stage(uint32_t st, int r0, int n0, int m0, int t) {
    for (int i = t; i < 1024; i += 256) {
        const int row = i >> 3, q = i & 7;
        const uint32_t so = (uint32_t)(row * T_ROWB + q * 16);
        cpa16(st + OFF_Y + so, g_Yh + (size_t)(r0 + row) * NN + m0 + q * 8);
        cpa16(st + OFF_S + so, g_STh + (size_t)(n0 + row) * NN + m0 + q * 8);
    }
}

__global__ void __launch_bounds__(256) k_gemm_mma(float* __restrict__ out) {
    extern __shared__ char dsm[];
    const int t = threadIdx.x;
    const int r0 = blockIdx.x * 128;
    const int n0 = blockIdx.y * 128;
    __shared__ float s_c[128], s_sy[128];
    if (t < 128) { s_c[t] = g_c[n0 + t]; s_sy[t] = g_SY[r0 + t]; }
    const uint32_t sb = smem_u32(dsm);

    // Preload chunks 0,1 as two cp.async groups
    g_load_stage(sb, r0, n0, 0, t);
    asm volatile("cp.async.commit_group;" ::: "memory");
    g_load_stage(sb + STAGE_B, r0, n0, 64, t);
    asm volatile("cp.async.commit_group;" ::: "memory");

    const int L = t & 31, w = t >> 5;
    const int wr = (w >> 1) * 32;  // warp r base 0..96
    const int wn = (w & 1) * 64;   // warp n base 0/64
    const uint32_t a_l = (uint32_t)((wr + (L & 15)) * T_ROWB + ((L >> 4) * 8) * 2);
    const uint32_t b_l = (uint32_t)((wn + (L & 7) + ((L & 16) ? 8 : 0)) * T_ROWB + ((L & 8) ? 16 : 0));

    float acc[2][8][4] = {};

#pragma unroll 1
    for (int c = 0; c < 16; ++c) {
        if (c == 15) asm volatile("cp.async.wait_group 0;" ::: "memory");
        else         asm volatile("cp.async.wait_group 1;" ::: "memory");
        __syncthreads();
        const uint32_t st = sb + (uint32_t)(c & 1) * STAGE_B;
#pragma unroll
        for (int ks = 0; ks < 4; ++ks) {
            uint32_t ah[2][4], bh[4][4];
            const uint32_t ka = st + a_l + ks * 32;
            const uint32_t kb = st + b_l + ks * 32;
#pragma unroll
            for (int mt = 0; mt < 2; ++mt)
                ldm4(ah[mt], ka + OFF_Y + mt * (16 * T_ROWB));
#pragma unroll
            for (int bj = 0; bj < 4; ++bj)
                ldm4(bh[bj], kb + OFF_S + bj * (16 * T_ROWB));
#pragma unroll
            for (int mt = 0; mt < 2; ++mt)
#pragma unroll
                for (int nj = 0; nj < 8; ++nj)
                    mma_fp16(acc[mt][nj], ah[mt], &bh[nj >> 1][(nj & 1) * 2]);
        }
        __syncthreads();
        if (c + 2 < 16) {
            g_load_stage(st, r0, n0, (c + 2) * 64, t);
            asm volatile("cp.async.commit_group;" ::: "memory");
        }
    }

    // Epilogue: acc -> smem [n][r] (conflict-free), then coalesced float4 STG.
    float* so = (float*)dsm;
#pragma unroll
    for (int mt = 0; mt < 2; ++mt)
#pragma unroll
        for (int nj = 0; nj < 8; ++nj) {
            const int rl = wr + mt * 16 + (L >> 2);
            const int nl = wn + nj * 8 + (L & 3) * 2;
            so[nl * 132 + rl]           = acc[mt][nj][0];
            so[(nl + 1) * 132 + rl]     = acc[mt][nj][1];
            so[nl * 132 + rl + 8]       = acc[mt][nj][2];
            so[(nl + 1) * 132 + rl + 8] = acc[mt][nj][3];
        }
    __syncthreads();
    for (int i = t; i < 4096; i += 256) {
        const int n = i >> 5;
        const int rq = (i & 31) * 4;
        const float cn = s_c[n];
        float4 v;
        v.x = so[n * 132 + rq]     * A_INV_SCALE + cn * s_sy[rq];
        v.y = so[n * 132 + rq + 1] * A_INV_SCALE + cn * s_sy[rq + 1];
        v.z = so[n * 132 + rq + 2] * A_INV_SCALE + cn * s_sy[rq + 2];
        v.w = so[n * 132 + rq + 3] * A_INV_SCALE + cn * s_sy[rq + 3];
        const int r = r0 + rq;
        *(float4*)(out + (size_t)(r >> 6) * (NN * NK) + (size_t)(n0 + n) * NK + (r & 63)) = v;
    }
}

// ---------------------------------------------------------------------------
extern "C" void kernel_launch(void* const* d_in, const int* in_sizes, int n_in,
                              void* d_out, int out_size) {
    (void)in_sizes; (void)n_in; (void)out_size;
    const float* x        = (const float*)d_in[0];  // [B, N*K]
    const float* A_logits = (const float*)d_in[1];  // [N, N]
    const float* W1       = (const float*)d_in[2];  // [N, 8]
    const float* WV       = (const float*)d_in[3];  // [8, K, K]
    const float* gamma2   = (const float*)d_in[4];  // [N]
    const float* beta2    = (const float*)d_in[5];  // [N]
    float* out = (float*)d_out;

    static int smem_set = 0;
    if (!smem_set) {
        cudaFuncSetAttribute(k_gemm_mma, cudaFuncAttributeMaxDynamicSharedMemorySize,
                             2 * STAGE_B);
        smem_set = 1;
    }

    k_sink_row<<<NN, 256>>>(A_logits);
    k_sink_col<<<NN / 32, 256>>>();
    k_strans<<<dim3(32, 32), 256>>>();
    k_wsink<<<NN, 256>>>(W1, WV);
    k_xlocal<<<dim3(NN, NB / 64), 256>>>(x);
    k_lnt<<<dim3(NB, 2), 256>>>(gamma2, beta2);
    k_gemm_mma<<<dim3(128, 8), 256, 2 * STAGE_B>>>(out);
}

// round 11
// speedup vs baseline: 3.4665x; 1.0582x over previous
#include <cuda_runtime.h>
#include <cuda_bf16.h>
#include <cuda_fp16.h>
#include <math.h>
#include <stdint.h>

// Problem constants
#define NB 256        // batch B
#define NN 1024       // N
#define NK 64         // K
#define INV_TEMP 5.0f // 1/0.2
#define LN_EPS 1e-5f
#define A_SCALE 4096.0f
#define A_INV_SCALE 2.44140625e-4f
#define WP_SCALE 16384.0f
#define WP_INV (1.0f / 16384.0f)

// Scratch (static device globals; allocation inside kernel_launch is forbidden)
static __device__ float g_S[NN * NN];                    // sinkhorn(A_logits) 4 MB
static __device__ __half g_WT[(size_t)NN * NK * NK];     // (W - cW)^T *16384 fp16 [n][o][i] 8 MB
static __device__ float g_cW[NN * NK];                   // per-block W column means 256 KB
static __device__ float g_XL[(size_t)NB * NN * NK];      // x_local [b][n][k] 64 MB
static __device__ __half g_Yh[(size_t)NB * NK * NN];     // Y fp16 [r][m] 32 MB
static __device__ __half g_STh[NN * NN];                 // (S-c)^T * 4096, fp16 [n][m] 2 MB
static __device__ float g_c[NN];                         // column means of S
static __device__ float g_SY[NB * NK];                   // per-row sums of Y (exact fp32)

// ============================ PTX helpers (sm_80-era only!) ============================
__device__ __forceinline__ uint32_t smem_u32(const void* p) {
    uint32_t a;
    asm("{ .reg .u64 t; cvta.to.shared.u64 t, %1; cvt.u32.u64 %0, t; }" : "=r"(a) : "l"(p));
    return a;
}
__device__ __forceinline__ void cpa16(uint32_t s, const void* g) {
    asm volatile("cp.async.cg.shared.global [%0], [%1], 16;" :: "r"(s), "l"(g));
}
__device__ __forceinline__ void ldm4(uint32_t* r, uint32_t a) {
    asm volatile("ldmatrix.sync.aligned.m8n8.x4.shared.b16 {%0,%1,%2,%3}, [%4];"
                 : "=r"(r[0]), "=r"(r[1]), "=r"(r[2]), "=r"(r[3]) : "r"(a));
}
__device__ __forceinline__ void mma_fp16(float* d, const uint32_t* a, const uint32_t* b) {
    asm volatile(
        "mma.sync.aligned.m16n8k16.row.col.f32.f16.f16.f32 "
        "{%0,%1,%2,%3}, {%4,%5,%6,%7}, {%8,%9}, {%0,%1,%2,%3};"
        : "+f"(d[0]), "+f"(d[1]), "+f"(d[2]), "+f"(d[3])
        : "r"(a[0]), "r"(a[1]), "r"(a[2]), "r"(a[3]), "r"(b[0]), "r"(b[1]));
}

// ---------------------------------------------------------------------------
// Kernel 1: row pass of log_sinkhorn on A_logits.
// ---------------------------------------------------------------------------
__global__ void k_sink_row(const float* __restrict__ logits) {
    const int row = blockIdx.x;
    const int t = threadIdx.x;
    const float* rp = logits + (size_t)row * NN;
    float v[4];
    float m = -1e30f;
#pragma unroll
    for (int q = 0; q < 4; ++q) {
        v[q] = rp[t + 256 * q] * INV_TEMP;
        m = fmaxf(m, v[q]);
    }
    __shared__ float red[256];
    red[t] = m;
    __syncthreads();
    for (int s = 128; s > 0; s >>= 1) {
        if (t < s) red[t] = fmaxf(red[t], red[t + s]);
        __syncthreads();
    }
    m = red[0];
    __syncthreads();
    float acc = 0.f;
#pragma unroll
    for (int q = 0; q < 4; ++q) acc += expf(v[q] - m);
    red[t] = acc;
    __syncthreads();
    for (int s = 128; s > 0; s >>= 1) {
        if (t < s) red[t] += red[t + s];
        __syncthreads();
    }
    const float lse = logf(red[0]) + m;
    float* op = g_S + (size_t)row * NN;
#pragma unroll
    for (int q = 0; q < 4; ++q) op[t + 256 * q] = v[q] - lse;
}

// ---------------------------------------------------------------------------
// Kernel 2: column pass + exp + column means into g_c.
// ---------------------------------------------------------------------------
__global__ void k_sink_col() {
    const int c0 = blockIdx.x * 32;
    const int t = threadIdx.x;
    const int c = t & 31;
    const int ry = t >> 5;  // 0..7
    float m = -1e30f, s = 0.f;
    for (int i = ry; i < NN; i += 8) {
        float v = g_S[(size_t)i * NN + c0 + c];
        float mn = fmaxf(m, v);
        s = s * expf(m - mn) + expf(v - mn);
        m = mn;
    }
    __shared__ float sm[8][32];
    __shared__ float ss[8][32];
    __shared__ float cl[32];
    sm[ry][c] = m;
    ss[ry][c] = s;
    __syncthreads();
    if (t < 32) {
        float M = -1e30f;
#pragma unroll
        for (int q = 0; q < 8; ++q) M = fmaxf(M, sm[q][t]);
        float S = 0.f;
#pragma unroll
        for (int q = 0; q < 8; ++q) S += ss[q][t] * expf(sm[q][t] - M);
        cl[t] = logf(S) + M;
    }
    __syncthreads();
    const float myl = cl[c];
    float csum = 0.f;
    for (int i = ry; i < NN; i += 8) {
        size_t idx = (size_t)i * NN + c0 + c;
        float e = expf(g_S[idx] - myl);
        g_S[idx] = e;
        csum += e;
    }
    __syncthreads();
    ss[ry][c] = csum;
    __syncthreads();
    if (t < 32) {
        float S = 0.f;
#pragma unroll
        for (int q = 0; q < 8; ++q) S += ss[q][t];
        g_c[c0 + t] = S * (1.0f / NN);
    }
}

// ---------------------------------------------------------------------------
// Kernel 2b: STh[n][m] = (S[m][n] - c[n]) * A_SCALE, fp16.
// ---------------------------------------------------------------------------
__global__ void k_strans() {
    const int m0 = blockIdx.x * 32, n0 = blockIdx.y * 32;
    const int t = threadIdx.x;
    const int j = t & 31, i0 = t >> 5;
    __shared__ float T[32][33];
#pragma unroll
    for (int p = 0; p < 4; ++p)
        T[i0 + 8 * p][j] = g_S[(size_t)(m0 + i0 + 8 * p) * NN + n0 + j];
    __syncthreads();
#pragma unroll
    for (int p = 0; p < 4; ++p) {
        int nl = i0 + 8 * p;
        float v = (T[j][nl] - g_c[n0 + nl]) * A_SCALE;
        g_STh[(size_t)(n0 + nl) * NN + m0 + j] = __float2half(v);
    }
}

// ---------------------------------------------------------------------------
// Kernel 3: per-block sinkhorn of W1.W_V; emits mean-subtracted, scaled fp16
// W'^T [n][o][i] plus fp32 column means cW [n][o]. Parallel LSEs (4 thr/line).
// ---------------------------------------------------------------------------
__global__ void k_wsink(const float* __restrict__ W1, const float* __restrict__ WV) {
    const int n = blockIdx.x;
    const int t = threadIdx.x;
    __shared__ float L[64][65];
    __shared__ float w1[8];
    __shared__ float rl[64], cl[64], cw[64];
    __shared__ float redc[4][64];
    if (t < 8) w1[t] = W1[n * 8 + t];
    __syncthreads();
#pragma unroll
    for (int q = 0; q < 16; ++q) {
        int idx = t + 256 * q;
        float acc = 0.f;
#pragma unroll
        for (int k = 0; k < 8; ++k) acc += w1[k] * WV[k * 4096 + idx];
        L[idx >> 6][idx & 63] = acc * INV_TEMP;
    }
    __syncthreads();
    // row LSE (over o): 4 threads per row
    {
        const int r = t >> 2, j0 = (t & 3) * 16;
        float m = -1e30f;
#pragma unroll
        for (int e = 0; e < 16; ++e) m = fmaxf(m, L[r][j0 + e]);
        float s = 0.f;
#pragma unroll
        for (int e = 0; e < 16; ++e) s += expf(L[r][j0 + e] - m);
#pragma unroll
        for (int off = 1; off < 4; off <<= 1) {
            float mo = __shfl_xor_sync(0xffffffffu, m, off);
            float so = __shfl_xor_sync(0xffffffffu, s, off);
            float M = fmaxf(m, mo);
            s = s * expf(m - M) + so * expf(mo - M);
            m = M;
        }
        if ((t & 3) == 0) rl[r] = logf(s) + m;
    }
    __syncthreads();
#pragma unroll
    for (int q = 0; q < 16; ++q) {
        int idx = t + 256 * q;
        L[idx >> 6][idx & 63] -= rl[idx >> 6];
    }
    __syncthreads();
    // col LSE (over d): 4 threads per column
    {
        const int c = t >> 2, j0 = (t & 3) * 16;
        float m = -1e30f;
#pragma unroll
        for (int e = 0; e < 16; ++e) m = fmaxf(m, L[j0 + e][c]);
        float s = 0.f;
#pragma unroll
        for (int e = 0; e < 16; ++e) s += expf(L[j0 + e][c] - m);
#pragma unroll
        for (int off = 1; off < 4; off <<= 1) {
            float mo = __shfl_xor_sync(0xffffffffu, m, off);
            float so = __shfl_xor_sync(0xffffffffu, s, off);
            float M = fmaxf(m, mo);
            s = s * expf(m - M) + so * expf(mo - M);
            m = M;
        }
        if ((t & 3) == 0) cl[c] = logf(s) + m;
    }
    __syncthreads();
    // W = exp(L - cl) in place
#pragma unroll
    for (int q = 0; q < 16; ++q) {
        int idx = t + 256 * q;
        L[idx >> 6][idx & 63] = expf(L[idx >> 6][idx & 63] - cl[idx & 63]);
    }
    __syncthreads();
    // column means over d (input index)
    {
        const int o = t & 63, p = t >> 6;
        float s = 0.f;
#pragma unroll
        for (int e = 0; e < 16; ++e) s += L[p * 16 + e][o];
        redc[p][o] = s;
    }
    __syncthreads();
    if (t < 64) {
        float s = (redc[0][t] + redc[1][t]) + (redc[2][t] + redc[3][t]);
        float m = s * (1.0f / 64.0f);
        cw[t] = m;
        g_cW[n * 64 + t] = m;
    }
    __syncthreads();
    // W'^T[o][d] = (W[d][o] - cw[o]) * WP_SCALE, fp16
    __half* wt = g_WT + (size_t)n * 4096;
#pragma unroll
    for (int q = 0; q < 16; ++q) {
        int idx = t + 256 * q;
        int o = idx >> 6, d = idx & 63;
        wt[idx] = __float2half((L[d][o] - cw[o]) * WP_SCALE);
    }
}

// ---------------------------------------------------------------------------
// Kernel 4: x_local[b,n,o] = sx[b,n]*cW[n,o] + (x_fp16 @ W'^T)*WP_INV via
// fp16 tensor-core MMA. Block: one n, 64 batch rows; 8 warps, warp 16x32.
// ---------------------------------------------------------------------------
__global__ void __launch_bounds__(256) k_xlocal(const float* __restrict__ x) {
    const int n = blockIdx.x;
    const int b0 = blockIdx.y * 64;
    const int t = threadIdx.x;
    const int L = t & 31, w = t >> 5;
    __shared__ __align__(16) __half Xs[64 * 72];
    __shared__ __align__(16) __half Ws[64 * 72];
    __shared__ float sxs[64];
    __shared__ float cws[64];

    // Load X rows (fp32 -> fp16) + exact fp32 row sums. 4 threads per row.
    {
        const int row = t >> 2, c0 = (t & 3) * 16;
        const float* xp = x + (size_t)(b0 + row) * (NN * NK) + n * NK + c0;
        float4 v0 = *(const float4*)(xp + 0);
        float4 v1 = *(const float4*)(xp + 4);
        float4 v2 = *(const float4*)(xp + 8);
        float4 v3 = *(const float4*)(xp + 12);
        float s = ((v0.x + v0.y) + (v0.z + v0.w)) + ((v1.x + v1.y) + (v1.z + v1.w)) +
                  ((v2.x + v2.y) + (v2.z + v2.w)) + ((v3.x + v3.y) + (v3.z + v3.w));
        __half2* xs = (__half2*)(Xs + row * 72 + c0);
        xs[0] = __floats2half2_rn(v0.x, v0.y);
        xs[1] = __floats2half2_rn(v0.z, v0.w);
        xs[2] = __floats2half2_rn(v1.x, v1.y);
        xs[3] = __floats2half2_rn(v1.z, v1.w);
        xs[4] = __floats2half2_rn(v2.x, v2.y);
        xs[5] = __floats2half2_rn(v2.z, v2.w);
        xs[6] = __floats2half2_rn(v3.x, v3.y);
        xs[7] = __floats2half2_rn(v3.z, v3.w);
        s += __shfl_xor_sync(0xffffffffu, s, 1);
        s += __shfl_xor_sync(0xffffffffu, s, 2);
        if ((t & 3) == 0) sxs[row] = s;
    }
    // Load W'^T tile (fp16, rows o, cols i)
    {
        const __half* wp = g_WT + (size_t)n * 4096;
#pragma unroll
        for (int q = 0; q < 2; ++q) {
            int u = t + 256 * q;
            int row = u >> 3, c8 = (u & 7) * 8;
            *(uint4*)(Ws + row * 72 + c8) = *(const uint4*)(wp + u * 8);
        }
    }
    if (t < 64) cws[t] = g_cW[n * 64 + t];
    __syncthreads();

    const int m0 = (w >> 1) * 16;  // warp m-tile (b)
    const int wn = (w & 1) * 32;   // warp n-tile (o)
    const uint32_t xb = smem_u32(Xs), wb = smem_u32(Ws);
    const uint32_t a_l = xb + (uint32_t)((m0 + (L & 15)) * 144 + (L >> 4) * 16);
    const uint32_t b_l = wb + (uint32_t)((wn + (L & 7) + ((L & 16) ? 8 : 0)) * 144 +
                                         ((L & 8) ? 16 : 0));
    float acc[4][4] = {};
#pragma unroll
    for (int ks = 0; ks < 4; ++ks) {
        uint32_t ar[4], br[2][4];
        ldm4(ar, a_l + ks * 32);
        ldm4(br[0], b_l + ks * 32);
        ldm4(br[1], b_l + ks * 32 + 16 * 144);
#pragma unroll
        for (int nj = 0; nj < 4; ++nj)
            mma_fp16(acc[nj], ar, &br[nj >> 1][(nj & 1) * 2]);
    }

    // Epilogue: xl = acc*WP_INV + sx*cw
    const int r = L >> 2;
    const float sx0 = sxs[m0 + r], sx1 = sxs[m0 + r + 8];
    float* xl0 = g_XL + ((size_t)(b0 + m0 + r) * NN + n) * NK;
    float* xl1 = xl0 + (size_t)8 * NN * NK;
#pragma unroll
    for (int nj = 0; nj < 4; ++nj) {
        const int k = wn + nj * 8 + (L & 3) * 2;
        const float cw0 = cws[k], cw1 = cws[k + 1];
        float2 v0 = make_float2(acc[nj][0] * WP_INV + sx0 * cw0,
                                acc[nj][1] * WP_INV + sx0 * cw1);
        float2 v1 = make_float2(acc[nj][2] * WP_INV + sx1 * cw0,
                                acc[nj][3] * WP_INV + sx1 * cw1);
        *(float2*)(xl0 + k) = v0;
        *(float2*)(xl1 + k) = v1;
    }
}

// ---------------------------------------------------------------------------
// Kernel 5: layernorm over n (per (b,k)) + transpose; single global read via
// 128 KB smem slice. Emits fp16 Y [r][m] and exact fp32 row sums S_Y.
// ---------------------------------------------------------------------------
#define BUF_P 1025
__global__ void __launch_bounds__(256) k_lnt(const float* __restrict__ gamma2,
                                             const float* __restrict__ beta2) {
    extern __shared__ float buf[];  // [32][BUF_P]
    const int b = blockIdx.x;
    const int k0 = blockIdx.y * 32;
    const int t = threadIdx.x;
    const float* base = g_XL + (size_t)b * NN * NK + k0;
    // Load [1024 n][32 k] slice, transposed into buf[k][n]
    {
        const int c4 = (t & 7) * 4;
        const int nb = t >> 3;
#pragma unroll
        for (int q = 0; q < 32; ++q) {
            const int nn = nb + 32 * q;
            float4 v = *(const float4*)(base + (size_t)nn * NK + c4);
            buf[(c4 + 0) * BUF_P + nn] = v.x;
            buf[(c4 + 1) * BUF_P + nn] = v.y;
            buf[(c4 + 2) * BUF_P + nn] = v.z;
            buf[(c4 + 3) * BUF_P + nn] = v.w;
        }
    }
    __syncthreads();
    __shared__ float ps[8][32], ps2[8][32], mu[32], rs[32];
    {
        const int kc = t & 31, nr = t >> 5;
        float s = 0.f, s2 = 0.f;
        for (int nn = nr; nn < NN; nn += 8) {
            float v = buf[kc * BUF_P + nn];
            s += v;
            s2 += v * v;
        }
        ps[nr][kc] = s;
        ps2[nr][kc] = s2;
    }
    __syncthreads();
    if (t < 32) {
        float S = 0.f, S2 = 0.f;
#pragma unroll
        for (int q = 0; q < 8; ++q) { S += ps[q][t]; S2 += ps2[q][t]; }
        float m = S * (1.0f / NN);
        mu[t] = m;
        rs[t] = rsqrtf(S2 * (1.0f / NN) - m * m + LN_EPS);
    }
    __syncthreads();
    const int L = t & 31, w = t >> 5;
#pragma unroll
    for (int p = 0; p < 4; ++p) {
        const int kl = w + 8 * p;
        const float m = mu[kl], r = rs[kl];
        __half* yp = g_Yh + (size_t)(b * NK + k0 + kl) * NN;
        float sy = 0.f;
        for (int nn = L; nn < NN; nn += 32) {
            float v = (buf[kl * BUF_P + nn] - m) * r * gamma2[nn] + beta2[nn];
            sy += v;
            yp[nn] = __float2half(v);
        }
#pragma unroll
        for (int off = 16; off; off >>= 1) sy += __shfl_xor_sync(0xffffffffu, sy, off);
        if (L == 0) g_SY[b * NK + k0 + kl] = sy;
    }
}

// ---------------------------------------------------------------------------
// Kernel 6: single-pass fp16 tensor-core GEMM on mean-subtracted, scaled A'.
//   D[r][n] = sum_m Yh[r][m] * STh[n][m];  out = D/A_SCALE + c[n]*SY[r].
// CTA tile 128x128, K-chunk 64, double-buffered cp.async (72 KB smem).
// ---------------------------------------------------------------------------
#define T_ROWB 144
#define TILE_B (128 * T_ROWB)
#define STAGE_B (2 * TILE_B)
#define OFF_Y 0u
#define OFF_S ((uint32_t)TILE_B)

__device__ __forceinline__ void g_load_stage(uint32_t st, int r0, int n0, int m0, int t) {
    for (int i = t; i < 1024; i += 256) {
        const int row = i >> 3, q = i & 7;
        const uint32_t so = (uint32_t)(row * T_ROWB + q * 16);
        cpa16(st + OFF_Y + so, g_Yh + (size_t)(r0 + row) * NN + m0 + q * 8);
        cpa16(st + OFF_S + so, g_STh + (size_t)(n0 + row) * NN + m0 + q * 8);
    }
}

__global__ void __launch_bounds__(256) k_gemm_mma(float* __restrict__ out) {
    extern __shared__ char dsm[];
    const int t = threadIdx.x;
    const int r0 = blockIdx.x * 128;
    const int n0 = blockIdx.y * 128;
    __shared__ float s_c[128], s_sy[128];
    if (t < 128) { s_c[t] = g_c[n0 + t]; s_sy[t] = g_SY[r0 + t]; }
    const uint32_t sb = smem_u32(dsm);

    g_load_stage(sb, r0, n0, 0, t);
    asm volatile("cp.async.commit_group;" ::: "memory");
    g_load_stage(sb + STAGE_B, r0, n0, 64, t);
    asm volatile("cp.async.commit_group;" ::: "memory");

    const int L = t & 31, w = t >> 5;
    const int wr = (w >> 1) * 32;
    const int wn = (w & 1) * 64;
    const uint32_t a_l = (uint32_t)((wr + (L & 15)) * T_ROWB + ((L >> 4) * 8) * 2);
    const uint32_t b_l = (uint32_t)((wn + (L & 7) + ((L & 16) ? 8 : 0)) * T_ROWB + ((L & 8) ? 16 : 0));

    float acc[2][8][4] = {};

#pragma unroll 1
    for (int c = 0; c < 16; ++c) {
        if (c == 15) asm volatile("cp.async.wait_group 0;" ::: "memory");
        else         asm volatile("cp.async.wait_group 1;" ::: "memory");
        __syncthreads();
        const uint32_t st = sb + (uint32_t)(c & 1) * STAGE_B;
#pragma unroll
        for (int ks = 0; ks < 4; ++ks) {
            uint32_t ah[2][4], bh[4][4];
            const uint32_t ka = st + a_l + ks * 32;
            const uint32_t kb = st + b_l + ks * 32;
#pragma unroll
            for (int mt = 0; mt < 2; ++mt)
                ldm4(ah[mt], ka + OFF_Y + mt * (16 * T_ROWB));
#pragma unroll
            for (int bj = 0; bj < 4; ++bj)
                ldm4(bh[bj], kb + OFF_S + bj * (16 * T_ROWB));
#pragma unroll
            for (int mt = 0; mt < 2; ++mt)
#pragma unroll
                for (int nj = 0; nj < 8; ++nj)
                    mma_fp16(acc[mt][nj], ah[mt], &bh[nj >> 1][(nj & 1) * 2]);
        }
        __syncthreads();
        if (c + 2 < 16) {
            g_load_stage(st, r0, n0, (c + 2) * 64, t);
            asm volatile("cp.async.commit_group;" ::: "memory");
        }
    }

    // Epilogue: acc -> smem [n][r], then coalesced float4 STG.
    float* so = (float*)dsm;
#pragma unroll
    for (int mt = 0; mt < 2; ++mt)
#pragma unroll
        for (int nj = 0; nj < 8; ++nj) {
            const int rl = wr + mt * 16 + (L >> 2);
            const int nl = wn + nj * 8 + (L & 3) * 2;
            so[nl * 132 + rl]           = acc[mt][nj][0];
            so[(nl + 1) * 132 + rl]     = acc[mt][nj][1];
            so[nl * 132 + rl + 8]       = acc[mt][nj][2];
            so[(nl + 1) * 132 + rl + 8] = acc[mt][nj][3];
        }
    __syncthreads();
    for (int i = t; i < 4096; i += 256) {
        const int n = i >> 5;
        const int rq = (i & 31) * 4;
        const float cn = s_c[n];
        float4 v;
        v.x = so[n * 132 + rq]     * A_INV_SCALE + cn * s_sy[rq];
        v.y = so[n * 132 + rq + 1] * A_INV_SCALE + cn * s_sy[rq + 1];
        v.z = so[n * 132 + rq + 2] * A_INV_SCALE + cn * s_sy[rq + 2];
        v.w = so[n * 132 + rq + 3] * A_INV_SCALE + cn * s_sy[rq + 3];
        const int r = r0 + rq;
        *(float4*)(out + (size_t)(r >> 6) * (NN * NK) + (size_t)(n0 + n) * NK + (r & 63)) = v;
    }
}

// ---------------------------------------------------------------------------
extern "C" void kernel_launch(void* const* d_in, const int* in_sizes, int n_in,
                              void* d_out, int out_size) {
    (void)in_sizes; (void)n_in; (void)out_size;
    const float* x        = (const float*)d_in[0];  // [B, N*K]
    const float* A_logits = (const float*)d_in[1];  // [N, N]
    const float* W1       = (const float*)d_in[2];  // [N, 8]
    const float* WV       = (const float*)d_in[3];  // [8, K, K]
    const float* gamma2   = (const float*)d_in[4];  // [N]
    const float* beta2    = (const float*)d_in[5];  // [N]
    float* out = (float*)d_out;

    static int smem_set = 0;
    if (!smem_set) {
        cudaFuncSetAttribute(k_gemm_mma, cudaFuncAttributeMaxDynamicSharedMemorySize,
                             2 * STAGE_B);
        cudaFuncSetAttribute(k_lnt, cudaFuncAttributeMaxDynamicSharedMemorySize,
                             32 * BUF_P * 4);
        smem_set = 1;
    }

    k_sink_row<<<NN, 256>>>(A_logits);
    k_sink_col<<<NN / 32, 256>>>();
    k_strans<<<dim3(32, 32), 256>>>();
    k_wsink<<<NN, 256>>>(W1, WV);
    k_xlocal<<<dim3(NN, NB / 64), 256>>>(x);
    k_lnt<<<dim3(NB, 2), 256, 32 * BUF_P * 4>>>(gamma2, beta2);
    k_gemm_mma<<<dim3(128, 8), 256, 2 * STAGE_B>>>(out);
}

// round 12
// speedup vs baseline: 3.6289x; 1.0468x over previous
#include <cuda_runtime.h>
#include <cuda_bf16.h>
#include <cuda_fp16.h>
#include <math.h>
#include <stdint.h>

// Problem constants
#define NB 256        // batch B
#define NN 1024       // N
#define NK 64         // K
#define INV_TEMP 5.0f // 1/0.2
#define LN_EPS 1e-5f
#define A_SCALE 4096.0f
#define A_INV_SCALE 2.44140625e-4f
#define WP_SCALE 16384.0f
#define WP_INV (1.0f / 16384.0f)
#define C_N 9.765625e-4f   // 1/1024 exact
#define C_K 0.015625f      // 1/64 exact

// Scratch (static device globals; allocation inside kernel_launch is forbidden)
static __device__ float g_S[NN * NN];                    // row-stochastic P 4 MB
static __device__ __half g_WT[(size_t)NN * NK * NK];     // (W - 1/64)^T *16384 fp16 [n][o][i] 8 MB
static __device__ float g_XL[(size_t)NB * NN * NK];      // x_local [b][n][k] 64 MB
static __device__ __half g_Yh[(size_t)NB * NK * NN];     // Y fp16 [r][m] 32 MB
static __device__ __half g_STh[NN * NN];                 // (A - 1/1024)^T * 4096, fp16 [n][m] 2 MB
static __device__ float g_SY[NB * NK];                   // per-row sums of Y (exact fp32)

// ============================ PTX helpers (sm_80-era only!) ============================
__device__ __forceinline__ uint32_t smem_u32(const void* p) {
    uint32_t a;
    asm("{ .reg .u64 t; cvta.to.shared.u64 t, %1; cvt.u32.u64 %0, t; }" : "=r"(a) : "l"(p));
    return a;
}
__device__ __forceinline__ void cpa16(uint32_t s, const void* g) {
    asm volatile("cp.async.cg.shared.global [%0], [%1], 16;" :: "r"(s), "l"(g));
}
__device__ __forceinline__ void ldm4(uint32_t* r, uint32_t a) {
    asm volatile("ldmatrix.sync.aligned.m8n8.x4.shared.b16 {%0,%1,%2,%3}, [%4];"
                 : "=r"(r[0]), "=r"(r[1]), "=r"(r[2]), "=r"(r[3]) : "r"(a));
}
__device__ __forceinline__ void mma_fp16(float* d, const uint32_t* a, const uint32_t* b) {
    asm volatile(
        "mma.sync.aligned.m16n8k16.row.col.f32.f16.f16.f32 "
        "{%0,%1,%2,%3}, {%4,%5,%6,%7}, {%8,%9}, {%0,%1,%2,%3};"
        : "+f"(d[0]), "+f"(d[1]), "+f"(d[2]), "+f"(d[3])
        : "r"(a[0]), "r"(a[1]), "r"(a[2]), "r"(a[3]), "r"(b[0]), "r"(b[1]));
}

// ---------------------------------------------------------------------------
// Kernel 1: row pass. P[row] = exp(logits/T) / rowsum — linear domain, exp
// computed once and reused for both sum and output. (|logits/T| <= ~0.3.)
// ---------------------------------------------------------------------------
__global__ void k_sink_row(const float* __restrict__ logits) {
    const int row = blockIdx.x;
    const int t = threadIdx.x;
    const float* rp = logits + (size_t)row * NN;
    float e[4];
    float acc = 0.f;
#pragma unroll
    for (int q = 0; q < 4; ++q) {
        e[q] = expf(rp[t + 256 * q] * INV_TEMP);
        acc += e[q];
    }
    __shared__ float red[256];
    red[t] = acc;
    __syncthreads();
    for (int s = 128; s > 0; s >>= 1) {
        if (t < s) red[t] += red[t + s];
        __syncthreads();
    }
    const float rinv = 1.0f / red[0];
    float* op = g_S + (size_t)row * NN;
#pragma unroll
    for (int q = 0; q < 4; ++q) op[t + 256 * q] = e[q] * rinv;
}

// ---------------------------------------------------------------------------
// Kernel 2: column normalize + emit STh[n][m] = (P[m][n]/colsum - 1/1024)*4096
// directly (transposed, fp16) via a 135 KB smem buffer. No exp at all.
// ---------------------------------------------------------------------------
#define CP 33
__global__ void __launch_bounds__(256) k_sink_colT() {
    extern __shared__ float buf[];  // [1024][CP]
    const int c0 = blockIdx.x * 32;
    const int t = threadIdx.x;
    const int c = t & 31, ry = t >> 5;
    float csum = 0.f;
    for (int m = ry; m < NN; m += 8) {
        float v = g_S[(size_t)m * NN + c0 + c];
        buf[m * CP + c] = v;
        csum += v;
    }
    __shared__ float ss[8][32];
    __shared__ float cinv[32];
    ss[ry][c] = csum;
    __syncthreads();
    if (t < 32) {
        float S = 0.f;
#pragma unroll
        for (int q = 0; q < 8; ++q) S += ss[q][t];
        cinv[t] = 1.0f / S;
    }
    __syncthreads();
    const int w = t >> 5, L = t & 31;
#pragma unroll
    for (int j = 0; j < 4; ++j) {
        const int cc = w * 4 + j;
        const float ci = cinv[cc] * A_SCALE;  // STh = P*ci - 4  (A_SCALE/1024 = 4)
        __half2* op = (__half2*)(g_STh + (size_t)(c0 + cc) * NN);
#pragma unroll
        for (int q = 0; q < 16; ++q) {
            const int m = 2 * L + 64 * q;
            float a = buf[m * CP + cc] * ci - 4.0f;
            float b = buf[(m + 1) * CP + cc] * ci - 4.0f;
            op[m >> 1] = __floats2half2_rn(a, b);
        }
    }
}

// ---------------------------------------------------------------------------
// Kernel 3: per-block sinkhorn of W1.W_V, linear domain (exp once, 2 rcps).
// Emits W'^T = (W - 1/64)*WP_SCALE fp16 [n][o][i]. Column sums of W are
// exactly 1 (last step is column normalization) so colmean = 1/64 exactly.
// ---------------------------------------------------------------------------
__global__ void k_wsink(const float* __restrict__ W1, const float* __restrict__ WV) {
    const int n = blockIdx.x;
    const int t = threadIdx.x;
    __shared__ float L[64][65];
    __shared__ float w1[8];
    __shared__ float rinv[64], cinv[64];
    __shared__ float redc[4][64];
    if (t < 8) w1[t] = W1[n * 8 + t];
    __syncthreads();
#pragma unroll
    for (int q = 0; q < 16; ++q) {
        int idx = t + 256 * q;
        float acc = 0.f;
#pragma unroll
        for (int k = 0; k < 8; ++k) acc += w1[k] * WV[k * 4096 + idx];
        L[idx >> 6][idx & 63] = expf(acc * INV_TEMP);
    }
    __syncthreads();
    // row sums (over o): 4 threads per row
    {
        const int r = t >> 2, j0 = (t & 3) * 16;
        float s = 0.f;
#pragma unroll
        for (int e = 0; e < 16; ++e) s += L[r][j0 + e];
        s += __shfl_xor_sync(0xffffffffu, s, 1);
        s += __shfl_xor_sync(0xffffffffu, s, 2);
        if ((t & 3) == 0) rinv[r] = 1.0f / s;
    }
    __syncthreads();
    // scale rows + column partial sums
    {
        const int o = t & 63, p = t >> 6;
        float cs = 0.f;
#pragma unroll
        for (int e = 0; e < 16; ++e) {
            const int d = p * 16 + e;
            float f = L[d][o] * rinv[d];
            L[d][o] = f;
            cs += f;
        }
        redc[p][o] = cs;
    }
    __syncthreads();
    if (t < 64)
        cinv[t] = 1.0f / ((redc[0][t] + redc[1][t]) + (redc[2][t] + redc[3][t]));
    __syncthreads();
    __half* wt = g_WT + (size_t)n * 4096;
#pragma unroll
    for (int q = 0; q < 16; ++q) {
        int idx = t + 256 * q;
        int o = idx >> 6, d = idx & 63;
        wt[idx] = __float2half((L[d][o] * cinv[o] - C_K) * WP_SCALE);
    }
}

// ---------------------------------------------------------------------------
// Kernel 4: x_local[b,n,o] = sx[b,n]/64 + (x_fp16 @ W'^T)*WP_INV via fp16 MMA.
// ---------------------------------------------------------------------------
__global__ void __launch_bounds__(256) k_xlocal(const float* __restrict__ x) {
    const int n = blockIdx.x;
    const int b0 = blockIdx.y * 64;
    const int t = threadIdx.x;
    const int L = t & 31, w = t >> 5;
    __shared__ __align__(16) __half Xs[64 * 72];
    __shared__ __align__(16) __half Ws[64 * 72];
    __shared__ float sxs[64];

    {
        const int row = t >> 2, c0 = (t & 3) * 16;
        const float* xp = x + (size_t)(b0 + row) * (NN * NK) + n * NK + c0;
        float4 v0 = *(const float4*)(xp + 0);
        float4 v1 = *(const float4*)(xp + 4);
        float4 v2 = *(const float4*)(xp + 8);
        float4 v3 = *(const float4*)(xp + 12);
        float s = ((v0.x + v0.y) + (v0.z + v0.w)) + ((v1.x + v1.y) + (v1.z + v1.w)) +
                  ((v2.x + v2.y) + (v2.z + v2.w)) + ((v3.x + v3.y) + (v3.z + v3.w));
        __half2* xs = (__half2*)(Xs + row * 72 + c0);
        xs[0] = __floats2half2_rn(v0.x, v0.y);
        xs[1] = __floats2half2_rn(v0.z, v0.w);
        xs[2] = __floats2half2_rn(v1.x, v1.y);
        xs[3] = __floats2half2_rn(v1.z, v1.w);
        xs[4] = __floats2half2_rn(v2.x, v2.y);
        xs[5] = __floats2half2_rn(v2.z, v2.w);
        xs[6] = __floats2half2_rn(v3.x, v3.y);
        xs[7] = __floats2half2_rn(v3.z, v3.w);
        s += __shfl_xor_sync(0xffffffffu, s, 1);
        s += __shfl_xor_sync(0xffffffffu, s, 2);
        if ((t & 3) == 0) sxs[row] = s;
    }
    {
        const __half* wp = g_WT + (size_t)n * 4096;
#pragma unroll
        for (int q = 0; q < 2; ++q) {
            int u = t + 256 * q;
            int row = u >> 3, c8 = (u & 7) * 8;
            *(uint4*)(Ws + row * 72 + c8) = *(const uint4*)(wp + u * 8);
        }
    }
    __syncthreads();

    const int m0 = (w >> 1) * 16;
    const int wn = (w & 1) * 32;
    const uint32_t xb = smem_u32(Xs), wb = smem_u32(Ws);
    const uint32_t a_l = xb + (uint32_t)((m0 + (L & 15)) * 144 + (L >> 4) * 16);
    const uint32_t b_l = wb + (uint32_t)((wn + (L & 7) + ((L & 16) ? 8 : 0)) * 144 +
                                         ((L & 8) ? 16 : 0));
    float acc[4][4] = {};
#pragma unroll
    for (int ks = 0; ks < 4; ++ks) {
        uint32_t ar[4], br[2][4];
        ldm4(ar, a_l + ks * 32);
        ldm4(br[0], b_l + ks * 32);
        ldm4(br[1], b_l + ks * 32 + 16 * 144);
#pragma unroll
        for (int nj = 0; nj < 4; ++nj)
            mma_fp16(acc[nj], ar, &br[nj >> 1][(nj & 1) * 2]);
    }

    const int r = L >> 2;
    const float sx0 = sxs[m0 + r] * C_K, sx1 = sxs[m0 + r + 8] * C_K;
    float* xl0 = g_XL + ((size_t)(b0 + m0 + r) * NN + n) * NK;
    float* xl1 = xl0 + (size_t)8 * NN * NK;
#pragma unroll
    for (int nj = 0; nj < 4; ++nj) {
        const int k = wn + nj * 8 + (L & 3) * 2;
        float2 v0 = make_float2(acc[nj][0] * WP_INV + sx0, acc[nj][1] * WP_INV + sx0);
        float2 v1 = make_float2(acc[nj][2] * WP_INV + sx1, acc[nj][3] * WP_INV + sx1);
        *(float2*)(xl0 + k) = v0;
        *(float2*)(xl1 + k) = v1;
    }
}

// ---------------------------------------------------------------------------
// Kernel 5: layernorm over n (per (b,k)) + transpose via 128 KB smem slice.
// Emits fp16 Y [r][m] and exact fp32 row sums S_Y.
// ---------------------------------------------------------------------------
#define BUF_P 1025
__global__ void __launch_bounds__(256) k_lnt(const float* __restrict__ gamma2,
                                             const float* __restrict__ beta2) {
    extern __shared__ float buf[];  // [32][BUF_P]
    const int b = blockIdx.x;
    const int k0 = blockIdx.y * 32;
    const int t = threadIdx.x;
    const float* base = g_XL + (size_t)b * NN * NK + k0;
    {
        const int c4 = (t & 7) * 4;
        const int nb = t >> 3;
#pragma unroll
        for (int q = 0; q < 32; ++q) {
            const int nn = nb + 32 * q;
            float4 v = *(const float4*)(base + (size_t)nn * NK + c4);
            buf[(c4 + 0) * BUF_P + nn] = v.x;
            buf[(c4 + 1) * BUF_P + nn] = v.y;
            buf[(c4 + 2) * BUF_P + nn] = v.z;
            buf[(c4 + 3) * BUF_P + nn] = v.w;
        }
    }
    __syncthreads();
    __shared__ float ps[8][32], ps2[8][32], mu[32], rs[32];
    {
        const int kc = t & 31, nr = t >> 5;
        float s = 0.f, s2 = 0.f;
        for (int nn = nr; nn < NN; nn += 8) {
            float v = buf[kc * BUF_P + nn];
            s += v;
            s2 += v * v;
        }
        ps[nr][kc] = s;
        ps2[nr][kc] = s2;
    }
    __syncthreads();
    if (t < 32) {
        float S = 0.f, S2 = 0.f;
#pragma unroll
        for (int q = 0; q < 8; ++q) { S += ps[q][t]; S2 += ps2[q][t]; }
        float m = S * (1.0f / NN);
        mu[t] = m;
        rs[t] = rsqrtf(S2 * (1.0f / NN) - m * m + LN_EPS);
    }
    __syncthreads();
    const int L = t & 31, w = t >> 5;
#pragma unroll
    for (int p = 0; p < 4; ++p) {
        const int kl = w + 8 * p;
        const float m = mu[kl], r = rs[kl];
        __half* yp = g_Yh + (size_t)(b * NK + k0 + kl) * NN;
        float sy = 0.f;
        for (int nn = L; nn < NN; nn += 32) {
            float v = (buf[kl * BUF_P + nn] - m) * r * gamma2[nn] + beta2[nn];
            sy += v;
            yp[nn] = __float2half(v);
        }
#pragma unroll
        for (int off = 16; off; off >>= 1) sy += __shfl_xor_sync(0xffffffffu, sy, off);
        if (L == 0) g_SY[b * NK + k0 + kl] = sy;
    }
}

// ---------------------------------------------------------------------------
// Kernel 6: single-pass fp16 tensor-core GEMM, 3-stage cp.async pipeline.
//   D[r][n] = sum_m Yh[r][m] * STh[n][m];  out = D/A_SCALE + SY[r]/1024.
// CTA tile 128x128, K-chunk 64, 108 KB smem (2 CTAs/SM possible).
// ---------------------------------------------------------------------------
#define T_ROWB 144
#define TILE_B (128 * T_ROWB)
#define STAGE_B (2 * TILE_B)
#define OFF_Y 0u
#define OFF_S ((uint32_t)TILE_B)

__device__ __forceinline__ void g_load_stage(uint32_t st, int r0, int n0, int m0, int t) {
    for (int i = t; i < 1024; i += 256) {
        const int row = i >> 3, q = i & 7;
        const uint32_t so = (uint32_t)(row * T_ROWB + q * 16);
        cpa16(st + OFF_Y + so, g_Yh + (size_t)(r0 + row) * NN + m0 + q * 8);
        cpa16(st + OFF_S + so, g_STh + (size_t)(n0 + row) * NN + m0 + q * 8);
    }
}

__global__ void __launch_bounds__(256) k_gemm_mma(float* __restrict__ out) {
    extern __shared__ char dsm[];
    const int t = threadIdx.x;
    const int r0 = blockIdx.x * 128;
    const int n0 = blockIdx.y * 128;
    __shared__ float s_sy[128];
    if (t < 128) s_sy[t] = g_SY[r0 + t] * C_N;
    const uint32_t sb = smem_u32(dsm);

    // Preload chunks 0,1,2
    g_load_stage(sb, r0, n0, 0, t);
    asm volatile("cp.async.commit_group;" ::: "memory");
    g_load_stage(sb + STAGE_B, r0, n0, 64, t);
    asm volatile("cp.async.commit_group;" ::: "memory");
    g_load_stage(sb + 2 * STAGE_B, r0, n0, 128, t);
    asm volatile("cp.async.commit_group;" ::: "memory");

    const int L = t & 31, w = t >> 5;
    const int wr = (w >> 1) * 32;
    const int wn = (w & 1) * 64;
    const uint32_t a_l = (uint32_t)((wr + (L & 15)) * T_ROWB + ((L >> 4) * 8) * 2);
    const uint32_t b_l = (uint32_t)((wn + (L & 7) + ((L & 16) ? 8 : 0)) * T_ROWB + ((L & 8) ? 16 : 0));

    float acc[2][8][4] = {};
    int stg = 0;

#pragma unroll 1
    for (int c = 0; c < 16; ++c) {
        if (c < 14)       asm volatile("cp.async.wait_group 2;" ::: "memory");
        else if (c == 14) asm volatile("cp.async.wait_group 1;" ::: "memory");
        else              asm volatile("cp.async.wait_group 0;" ::: "memory");
        __syncthreads();
        const uint32_t st = sb + (uint32_t)stg * STAGE_B;
#pragma unroll
        for (int ks = 0; ks < 4; ++ks) {
            uint32_t ah[2][4], bh[4][4];
            const uint32_t ka = st + a_l + ks * 32;
            const uint32_t kb = st + b_l + ks * 32;
#pragma unroll
            for (int mt = 0; mt < 2; ++mt)
                ldm4(ah[mt], ka + OFF_Y + mt * (16 * T_ROWB));
#pragma unroll
            for (int bj = 0; bj < 4; ++bj)
                ldm4(bh[bj], kb + OFF_S + bj * (16 * T_ROWB));
#pragma unroll
            for (int mt = 0; mt < 2; ++mt)
#pragma unroll
                for (int nj = 0; nj < 8; ++nj)
                    mma_fp16(acc[mt][nj], ah[mt], &bh[nj >> 1][(nj & 1) * 2]);
        }
        __syncthreads();
        if (c + 3 < 16) {
            g_load_stage(st, r0, n0, (c + 3) * 64, t);
            asm volatile("cp.async.commit_group;" ::: "memory");
        }
        stg = (stg == 2) ? 0 : stg + 1;
    }

    // Epilogue: acc -> smem [n][r], then coalesced float4 STG.
    float* so = (float*)dsm;
#pragma unroll
    for (int mt = 0; mt < 2; ++mt)
#pragma unroll
        for (int nj = 0; nj < 8; ++nj) {
            const int rl = wr + mt * 16 + (L >> 2);
            const int nl = wn + nj * 8 + (L & 3) * 2;
            so[nl * 132 + rl]           = acc[mt][nj][0];
            so[(nl + 1) * 132 + rl]     = acc[mt][nj][1];
            so[nl * 132 + rl + 8]       = acc[mt][nj][2];
            so[(nl + 1) * 132 + rl + 8] = acc[mt][nj][3];
        }
    __syncthreads();
    for (int i = t; i < 4096; i += 256) {
        const int n = i >> 5;
        const int rq = (i & 31) * 4;
        float4 v;
        v.x = so[n * 132 + rq]     * A_INV_SCALE + s_sy[rq];
        v.y = so[n * 132 + rq + 1] * A_INV_SCALE + s_sy[rq + 1];
        v.z = so[n * 132 + rq + 2] * A_INV_SCALE + s_sy[rq + 2];
        v.w = so[n * 132 + rq + 3] * A_INV_SCALE + s_sy[rq + 3];
        const int r = r0 + rq;
        *(float4*)(out + (size_t)(r >> 6) * (NN * NK) + (size_t)(n0 + n) * NK + (r & 63)) = v;
    }
}

// ---------------------------------------------------------------------------
extern "C" void kernel_launch(void* const* d_in, const int* in_sizes, int n_in,
                              void* d_out, int out_size) {
    (void)in_sizes; (void)n_in; (void)out_size;
    const float* x        = (const float*)d_in[0];  // [B, N*K]
    const float* A_logits = (const float*)d_in[1];  // [N, N]
    const float* W1       = (const float*)d_in[2];  // [N, 8]
    const float* WV       = (const float*)d_in[3];  // [8, K, K]
    const float* gamma2   = (const float*)d_in[4];  // [N]
    const float* beta2    = (const float*)d_in[5];  // [N]
    float* out = (float*)d_out;

    static int smem_set = 0;
    if (!smem_set) {
        cudaFuncSetAttribute(k_gemm_mma, cudaFuncAttributeMaxDynamicSharedMemorySize,
                             3 * STAGE_B);
        cudaFuncSetAttribute(k_lnt, cudaFuncAttributeMaxDynamicSharedMemorySize,
                             32 * BUF_P * 4);
        cudaFuncSetAttribute(k_sink_colT, cudaFuncAttributeMaxDynamicSharedMemorySize,
                             NN * CP * 4);
        smem_set = 1;
    }

    k_sink_row<<<NN, 256>>>(A_logits);
    k_sink_colT<<<32, 256, NN * CP * 4>>>();
    k_wsink<<<NN, 256>>>(W1, WV);
    k_xlocal<<<dim3(NN, NB / 64), 256>>>(x);
    k_lnt<<<dim3(NB, 2), 256, 32 * BUF_P * 4>>>(gamma2, beta2);
    k_gemm_mma<<<dim3(128, 8), 256, 3 * STAGE_B>>>(out);
}

// round 13
// speedup vs baseline: 3.8008x; 1.0474x over previous
#include <cuda_runtime.h>
#include <cuda_bf16.h>
#include <cuda_fp16.h>
#include <math.h>
#include <stdint.h>

// Problem constants
#define NB 256        // batch B
#define NN 1024       // N
#define NK 64         // K
#define INV_TEMP 5.0f // 1/0.2
#define LN_EPS 1e-5f
#define A_SCALE 4096.0f
#define A_INV_SCALE 2.44140625e-4f
#define WP_SCALE 16384.0f
#define WP_INV (1.0f / 16384.0f)
#define C_N 9.765625e-4f   // 1/1024 exact
#define C_K 0.015625f      // 1/64 exact

// Scratch (static device globals; allocation inside kernel_launch is forbidden)
static __device__ float g_S[NN * NN];                    // row-stochastic P 4 MB
static __device__ __half g_WT[(size_t)NN * NK * NK];     // (W - 1/64)^T *16384 fp16 [n][o][i] 8 MB
static __device__ __half g_XLh[(size_t)NB * NN * NK];    // x_local fp16 [b][n][k] 32 MB
static __device__ __half g_Yh[(size_t)NB * NK * NN];     // Y fp16 [r][m] 32 MB
static __device__ __half g_STh[NN * NN];                 // (A - 1/1024)^T * 4096, fp16 [n][m] 2 MB
static __device__ float g_SY[NB * NK];                   // per-row sums of Y (exact fp32)

// ============================ PTX helpers (sm_80-era only!) ============================
__device__ __forceinline__ uint32_t smem_u32(const void* p) {
    uint32_t a;
    asm("{ .reg .u64 t; cvta.to.shared.u64 t, %1; cvt.u32.u64 %0, t; }" : "=r"(a) : "l"(p));
    return a;
}
__device__ __forceinline__ void cpa16(uint32_t s, const void* g) {
    asm volatile("cp.async.cg.shared.global [%0], [%1], 16;" :: "r"(s), "l"(g));
}
__device__ __forceinline__ void ldm4(uint32_t* r, uint32_t a) {
    asm volatile("ldmatrix.sync.aligned.m8n8.x4.shared.b16 {%0,%1,%2,%3}, [%4];"
                 : "=r"(r[0]), "=r"(r[1]), "=r"(r[2]), "=r"(r[3]) : "r"(a));
}
__device__ __forceinline__ void mma_fp16(float* d, const uint32_t* a, const uint32_t* b) {
    asm volatile(
        "mma.sync.aligned.m16n8k16.row.col.f32.f16.f16.f32 "
        "{%0,%1,%2,%3}, {%4,%5,%6,%7}, {%8,%9}, {%0,%1,%2,%3};"
        : "+f"(d[0]), "+f"(d[1]), "+f"(d[2]), "+f"(d[3])
        : "r"(a[0]), "r"(a[1]), "r"(a[2]), "r"(a[3]), "r"(b[0]), "r"(b[1]));
}

// ---------------------------------------------------------------------------
// Kernel 1: row pass. P[row] = exp(logits/T) / rowsum — linear domain.
// ---------------------------------------------------------------------------
__global__ void k_sink_row(const float* __restrict__ logits) {
    const int row = blockIdx.x;
    const int t = threadIdx.x;
    const float* rp = logits + (size_t)row * NN;
    float e[4];
    float acc = 0.f;
#pragma unroll
    for (int q = 0; q < 4; ++q) {
        e[q] = expf(rp[t + 256 * q] * INV_TEMP);
        acc += e[q];
    }
    __shared__ float red[256];
    red[t] = acc;
    __syncthreads();
    for (int s = 128; s > 0; s >>= 1) {
        if (t < s) red[t] += red[t + s];
        __syncthreads();
    }
    const float rinv = 1.0f / red[0];
    float* op = g_S + (size_t)row * NN;
#pragma unroll
    for (int q = 0; q < 4; ++q) op[t + 256 * q] = e[q] * rinv;
}

// ---------------------------------------------------------------------------
// Kernel 2: column normalize + emit STh[n][m] = (P[m][n]/colsum - 1/1024)*4096
// directly (transposed, fp16) via a 135 KB smem buffer. No exp at all.
// ---------------------------------------------------------------------------
#define CP 33
__global__ void __launch_bounds__(256) k_sink_colT() {
    extern __shared__ float buf[];  // [1024][CP]
    const int c0 = blockIdx.x * 32;
    const int t = threadIdx.x;
    const int c = t & 31, ry = t >> 5;
    float csum = 0.f;
    for (int m = ry; m < NN; m += 8) {
        float v = g_S[(size_t)m * NN + c0 + c];
        buf[m * CP + c] = v;
        csum += v;
    }
    __shared__ float ss[8][32];
    __shared__ float cinv[32];
    ss[ry][c] = csum;
    __syncthreads();
    if (t < 32) {
        float S = 0.f;
#pragma unroll
        for (int q = 0; q < 8; ++q) S += ss[q][t];
        cinv[t] = 1.0f / S;
    }
    __syncthreads();
    const int w = t >> 5, L = t & 31;
#pragma unroll
    for (int j = 0; j < 4; ++j) {
        const int cc = w * 4 + j;
        const float ci = cinv[cc] * A_SCALE;  // STh = P*ci - 4  (A_SCALE/1024 = 4)
        __half2* op = (__half2*)(g_STh + (size_t)(c0 + cc) * NN);
#pragma unroll
        for (int q = 0; q < 16; ++q) {
            const int m = 2 * L + 64 * q;
            float a = buf[m * CP + cc] * ci - 4.0f;
            float b = buf[(m + 1) * CP + cc] * ci - 4.0f;
            op[m >> 1] = __floats2half2_rn(a, b);
        }
    }
}

// ---------------------------------------------------------------------------
// Kernel 3: per-block sinkhorn of W1.W_V, linear domain (exp once, 2 rcps).
// Emits W'^T = (W - 1/64)*WP_SCALE fp16 [n][o][i].
// ---------------------------------------------------------------------------
__global__ void k_wsink(const float* __restrict__ W1, const float* __restrict__ WV) {
    const int n = blockIdx.x;
    const int t = threadIdx.x;
    __shared__ float L[64][65];
    __shared__ float w1[8];
    __shared__ float rinv[64], cinv[64];
    __shared__ float redc[4][64];
    if (t < 8) w1[t] = W1[n * 8 + t];
    __syncthreads();
#pragma unroll
    for (int q = 0; q < 16; ++q) {
        int idx = t + 256 * q;
        float acc = 0.f;
#pragma unroll
        for (int k = 0; k < 8; ++k) acc += w1[k] * WV[k * 4096 + idx];
        L[idx >> 6][idx & 63] = expf(acc * INV_TEMP);
    }
    __syncthreads();
    {
        const int r = t >> 2, j0 = (t & 3) * 16;
        float s = 0.f;
#pragma unroll
        for (int e = 0; e < 16; ++e) s += L[r][j0 + e];
        s += __shfl_xor_sync(0xffffffffu, s, 1);
        s += __shfl_xor_sync(0xffffffffu, s, 2);
        if ((t & 3) == 0) rinv[r] = 1.0f / s;
    }
    __syncthreads();
    {
        const int o = t & 63, p = t >> 6;
        float cs = 0.f;
#pragma unroll
        for (int e = 0; e < 16; ++e) {
            const int d = p * 16 + e;
            float f = L[d][o] * rinv[d];
            L[d][o] = f;
            cs += f;
        }
        redc[p][o] = cs;
    }
    __syncthreads();
    if (t < 64)
        cinv[t] = 1.0f / ((redc[0][t] + redc[1][t]) + (redc[2][t] + redc[3][t]));
    __syncthreads();
    __half* wt = g_WT + (size_t)n * 4096;
#pragma unroll
    for (int q = 0; q < 16; ++q) {
        int idx = t + 256 * q;
        int o = idx >> 6, d = idx & 63;
        wt[idx] = __float2half((L[d][o] * cinv[o] - C_K) * WP_SCALE);
    }
}

// ---------------------------------------------------------------------------
// Kernel 4: x_local[b,n,o] = sx[b,n]/64 + (x_fp16 @ W'^T)*WP_INV via fp16 MMA.
// Output now fp16 [b][n][k] (LN over n has exact zero mean, so this
// quantization error never touches the 1/1024 bulk of A — see analysis).
// ---------------------------------------------------------------------------
__global__ void __launch_bounds__(256) k_xlocal(const float* __restrict__ x) {
    const int n = blockIdx.x;
    const int b0 = blockIdx.y * 64;
    const int t = threadIdx.x;
    const int L = t & 31, w = t >> 5;
    __shared__ __align__(16) __half Xs[64 * 72];
    __shared__ __align__(16) __half Ws[64 * 72];
    __shared__ float sxs[64];

    {
        const int row = t >> 2, c0 = (t & 3) * 16;
        const float* xp = x + (size_t)(b0 + row) * (NN * NK) + n * NK + c0;
        float4 v0 = *(const float4*)(xp + 0);
        float4 v1 = *(const float4*)(xp + 4);
        float4 v2 = *(const float4*)(xp + 8);
        float4 v3 = *(const float4*)(xp + 12);
        float s = ((v0.x + v0.y) + (v0.z + v0.w)) + ((v1.x + v1.y) + (v1.z + v1.w)) +
                  ((v2.x + v2.y) + (v2.z + v2.w)) + ((v3.x + v3.y) + (v3.z + v3.w));
        __half2* xs = (__half2*)(Xs + row * 72 + c0);
        xs[0] = __floats2half2_rn(v0.x, v0.y);
        xs[1] = __floats2half2_rn(v0.z, v0.w);
        xs[2] = __floats2half2_rn(v1.x, v1.y);
        xs[3] = __floats2half2_rn(v1.z, v1.w);
        xs[4] = __floats2half2_rn(v2.x, v2.y);
        xs[5] = __floats2half2_rn(v2.z, v2.w);
        xs[6] = __floats2half2_rn(v3.x, v3.y);
        xs[7] = __floats2half2_rn(v3.z, v3.w);
        s += __shfl_xor_sync(0xffffffffu, s, 1);
        s += __shfl_xor_sync(0xffffffffu, s, 2);
        if ((t & 3) == 0) sxs[row] = s;
    }
    {
        const __half* wp = g_WT + (size_t)n * 4096;
#pragma unroll
        for (int q = 0; q < 2; ++q) {
            int u = t + 256 * q;
            int row = u >> 3, c8 = (u & 7) * 8;
            *(uint4*)(Ws + row * 72 + c8) = *(const uint4*)(wp + u * 8);
        }
    }
    __syncthreads();

    const int m0 = (w >> 1) * 16;
    const int wn = (w & 1) * 32;
    const uint32_t xb = smem_u32(Xs), wb = smem_u32(Ws);
    const uint32_t a_l = xb + (uint32_t)((m0 + (L & 15)) * 144 + (L >> 4) * 16);
    const uint32_t b_l = wb + (uint32_t)((wn + (L & 7) + ((L & 16) ? 8 : 0)) * 144 +
                                         ((L & 8) ? 16 : 0));
    float acc[4][4] = {};
#pragma unroll
    for (int ks = 0; ks < 4; ++ks) {
        uint32_t ar[4], br[2][4];
        ldm4(ar, a_l + ks * 32);
        ldm4(br[0], b_l + ks * 32);
        ldm4(br[1], b_l + ks * 32 + 16 * 144);
#pragma unroll
        for (int nj = 0; nj < 4; ++nj)
            mma_fp16(acc[nj], ar, &br[nj >> 1][(nj & 1) * 2]);
    }

    const int r = L >> 2;
    const float sx0 = sxs[m0 + r] * C_K, sx1 = sxs[m0 + r + 8] * C_K;
    __half* xl0 = g_XLh + ((size_t)(b0 + m0 + r) * NN + n) * NK;
    __half* xl1 = xl0 + (size_t)8 * NN * NK;
#pragma unroll
    for (int nj = 0; nj < 4; ++nj) {
        const int k = wn + nj * 8 + (L & 3) * 2;
        *(__half2*)(xl0 + k) =
            __floats2half2_rn(acc[nj][0] * WP_INV + sx0, acc[nj][1] * WP_INV + sx0);
        *(__half2*)(xl1 + k) =
            __floats2half2_rn(acc[nj][2] * WP_INV + sx1, acc[nj][3] * WP_INV + sx1);
    }
}

// ---------------------------------------------------------------------------
// Kernel 5: layernorm over n (per (b,k)) + transpose via 131 KB smem slice.
// Reads fp16 XL, emits fp16 Y [r][m] and exact fp32 row sums S_Y.
// ---------------------------------------------------------------------------
#define BUF_P 1025
__global__ void __launch_bounds__(256) k_lnt(const float* __restrict__ gamma2,
                                             const float* __restrict__ beta2) {
    extern __shared__ float buf[];  // [32][BUF_P]
    const int b = blockIdx.x;
    const int k0 = blockIdx.y * 32;
    const int t = threadIdx.x;
    const __half* base = g_XLh + (size_t)b * NN * NK + k0;
    // Load [1024 n][32 k] fp16 slice, transposed into fp32 buf[k][n]
    {
        const int c8 = (t & 3) * 8;
        const int nb = t >> 2;  // 0..63
#pragma unroll
        for (int q = 0; q < 16; ++q) {
            const int nn = nb + 64 * q;
            uint4 v = *(const uint4*)(base + (size_t)nn * NK + c8);
            const __half2* h = (const __half2*)&v;
#pragma unroll
            for (int j = 0; j < 4; ++j) {
                float2 f = __half22float2(h[j]);
                buf[(c8 + 2 * j) * BUF_P + nn] = f.x;
                buf[(c8 + 2 * j + 1) * BUF_P + nn] = f.y;
            }
        }
    }
    __syncthreads();
    __shared__ float ps[8][32], ps2[8][32], mu[32], rs[32];
    {
        const int kc = t & 31, nr = t >> 5;
        float s = 0.f, s2 = 0.f;
        for (int nn = nr; nn < NN; nn += 8) {
            float v = buf[kc * BUF_P + nn];
            s += v;
            s2 += v * v;
        }
        ps[nr][kc] = s;
        ps2[nr][kc] = s2;
    }
    __syncthreads();
    if (t < 32) {
        float S = 0.f, S2 = 0.f;
#pragma unroll
        for (int q = 0; q < 8; ++q) { S += ps[q][t]; S2 += ps2[q][t]; }
        float m = S * (1.0f / NN);
        mu[t] = m;
        rs[t] = rsqrtf(S2 * (1.0f / NN) - m * m + LN_EPS);
    }
    __syncthreads();
    const int L = t & 31, w = t >> 5;
#pragma unroll
    for (int p = 0; p < 4; ++p) {
        const int kl = w + 8 * p;
        const float m = mu[kl], r = rs[kl];
        __half* yp = g_Yh + (size_t)(b * NK + k0 + kl) * NN;
        float sy = 0.f;
        for (int nn = L; nn < NN; nn += 32) {
            float v = (buf[kl * BUF_P + nn] - m) * r * gamma2[nn] + beta2[nn];
            sy += v;
            yp[nn] = __float2half(v);
        }
#pragma unroll
        for (int off = 16; off; off >>= 1) sy += __shfl_xor_sync(0xffffffffu, sy, off);
        if (L == 0) g_SY[b * NK + k0 + kl] = sy;
    }
}

// ---------------------------------------------------------------------------
// Kernel 6: single-pass fp16 tensor-core GEMM, 3-stage cp.async pipeline.
//   D[r][n] = sum_m Yh[r][m] * STh[n][m];  out = D/A_SCALE + SY[r]/1024.
// ---------------------------------------------------------------------------
#define T_ROWB 144
#define TILE_B (128 * T_ROWB)
#define STAGE_B (2 * TILE_B)
#define OFF_Y 0u
#define OFF_S ((uint32_t)TILE_B)

__device__ __forceinline__ void g_load_stage(uint32_t st, int r0, int n0, int m0, int t) {
    for (int i = t; i < 1024; i += 256) {
        const int row = i >> 3, q = i & 7;
        const uint32_t so = (uint32_t)(row * T_ROWB + q * 16);
        cpa16(st + OFF_Y + so, g_Yh + (size_t)(r0 + row) * NN + m0 + q * 8);
        cpa16(st + OFF_S + so, g_STh + (size_t)(n0 + row) * NN + m0 + q * 8);
    }
}

__global__ void __launch_bounds__(256) k_gemm_mma(float* __restrict__ out) {
    extern __shared__ char dsm[];
    const int t = threadIdx.x;
    const int r0 = blockIdx.x * 128;
    const int n0 = blockIdx.y * 128;
    __shared__ float s_sy[128];
    if (t < 128) s_sy[t] = g_SY[r0 + t] * C_N;
    const uint32_t sb = smem_u32(dsm);

    g_load_stage(sb, r0, n0, 0, t);
    asm volatile("cp.async.commit_group;" ::: "memory");
    g_load_stage(sb + STAGE_B, r0, n0, 64, t);
    asm volatile("cp.async.commit_group;" ::: "memory");
    g_load_stage(sb + 2 * STAGE_B, r0, n0, 128, t);
    asm volatile("cp.async.commit_group;" ::: "memory");

    const int L = t & 31, w = t >> 5;
    const int wr = (w >> 1) * 32;
    const int wn = (w & 1) * 64;
    const uint32_t a_l = (uint32_t)((wr + (L & 15)) * T_ROWB + ((L >> 4) * 8) * 2);
    const uint32_t b_l = (uint32_t)((wn + (L & 7) + ((L & 16) ? 8 : 0)) * T_ROWB + ((L & 8) ? 16 : 0));

    float acc[2][8][4] = {};
    int stg = 0;

#pragma unroll 1
    for (int c = 0; c < 16; ++c) {
        if (c < 14)       asm volatile("cp.async.wait_group 2;" ::: "memory");
        else if (c == 14) asm volatile("cp.async.wait_group 1;" ::: "memory");
        else              asm volatile("cp.async.wait_group 0;" ::: "memory");
        __syncthreads();
        const uint32_t st = sb + (uint32_t)stg * STAGE_B;
#pragma unroll
        for (int ks = 0; ks < 4; ++ks) {
            uint32_t ah[2][4], bh[4][4];
            const uint32_t ka = st + a_l + ks * 32;
            const uint32_t kb = st + b_l + ks * 32;
#pragma unroll
            for (int mt = 0; mt < 2; ++mt)
                ldm4(ah[mt], ka + OFF_Y + mt * (16 * T_ROWB));
#pragma unroll
            for (int bj = 0; bj < 4; ++bj)
                ldm4(bh[bj], kb + OFF_S + bj * (16 * T_ROWB));
#pragma unroll
            for (int mt = 0; mt < 2; ++mt)
#pragma unroll
                for (int nj = 0; nj < 8; ++nj)
                    mma_fp16(acc[mt][nj], ah[mt], &bh[nj >> 1][(nj & 1) * 2]);
        }
        __syncthreads();
        if (c + 3 < 16) {
            g_load_stage(st, r0, n0, (c + 3) * 64, t);
            asm volatile("cp.async.commit_group;" ::: "memory");
        }
        stg = (stg == 2) ? 0 : stg + 1;
    }

    // Epilogue: acc -> smem [n][r], then coalesced float4 STG.
    float* so = (float*)dsm;
#pragma unroll
    for (int mt = 0; mt < 2; ++mt)
#pragma unroll
        for (int nj = 0; nj < 8; ++nj) {
            const int rl = wr + mt * 16 + (L >> 2);
            const int nl = wn + nj * 8 + (L & 3) * 2;
            so[nl * 132 + rl]           = acc[mt][nj][0];
            so[(nl + 1) * 132 + rl]     = acc[mt][nj][1];
            so[nl * 132 + rl + 8]       = acc[mt][nj][2];
            so[(nl + 1) * 132 + rl + 8] = acc[mt][nj][3];
        }
    __syncthreads();
    for (int i = t; i < 4096; i += 256) {
        const int n = i >> 5;
        const int rq = (i & 31) * 4;
        float4 v;
        v.x = so[n * 132 + rq]     * A_INV_SCALE + s_sy[rq];
        v.y = so[n * 132 + rq + 1] * A_INV_SCALE + s_sy[rq + 1];
        v.z = so[n * 132 + rq + 2] * A_INV_SCALE + s_sy[rq + 2];
        v.w = so[n * 132 + rq + 3] * A_INV_SCALE + s_sy[rq + 3];
        const int r = r0 + rq;
        *(float4*)(out + (size_t)(r >> 6) * (NN * NK) + (size_t)(n0 + n) * NK + (r & 63)) = v;
    }
}

// ---------------------------------------------------------------------------
extern "C" void kernel_launch(void* const* d_in, const int* in_sizes, int n_in,
                              void* d_out, int out_size) {
    (void)in_sizes; (void)n_in; (void)out_size;
    const float* x        = (const float*)d_in[0];  // [B, N*K]
    const float* A_logits = (const float*)d_in[1];  // [N, N]
    const float* W1       = (const float*)d_in[2];  // [N, 8]
    const float* WV       = (const float*)d_in[3];  // [8, K, K]
    const float* gamma2   = (const float*)d_in[4];  // [N]
    const float* beta2    = (const float*)d_in[5];  // [N]
    float* out = (float*)d_out;

    static int smem_set = 0;
    if (!smem_set) {
        cudaFuncSetAttribute(k_gemm_mma, cudaFuncAttributeMaxDynamicSharedMemorySize,
                             3 * STAGE_B);
        cudaFuncSetAttribute(k_lnt, cudaFuncAttributeMaxDynamicSharedMemorySize,
                             32 * BUF_P * 4);
        cudaFuncSetAttribute(k_sink_colT, cudaFuncAttributeMaxDynamicSharedMemorySize,
                             NN * CP * 4);
        smem_set = 1;
    }

    k_sink_row<<<NN, 256>>>(A_logits);
    k_sink_colT<<<32, 256, NN * CP * 4>>>();
    k_wsink<<<NN, 256>>>(W1, WV);
    k_xlocal<<<dim3(NN, NB / 64), 256>>>(x);
    k_lnt<<<dim3(NB, 2), 256, 32 * BUF_P * 4>>>(gamma2, beta2);
    k_gemm_mma<<<dim3(128, 8), 256, 3 * STAGE_B>>>(out);
}

// round 14
// speedup vs baseline: 3.8415x; 1.0107x over previous
#include <cuda_runtime.h>
#include <cuda_bf16.h>
#include <cuda_fp16.h>
#include <math.h>
#include <stdint.h>

// Problem constants
#define NB 256        // batch B
#define NN 1024       // N
#define NK 64         // K
#define INV_TEMP 5.0f // 1/0.2
#define LN_EPS 1e-5f
#define A_SCALE 4096.0f
#define A_INV_SCALE 2.44140625e-4f
#define WP_SCALE 16384.0f
#define WP_INV (1.0f / 16384.0f)
#define C_N 9.765625e-4f   // 1/1024 exact
#define C_K 0.015625f      // 1/64 exact

// Scratch (static device globals; allocation inside kernel_launch is forbidden)
static __device__ float g_S[NN * NN];                    // row-stochastic P 4 MB
static __device__ __half g_WT[(size_t)NN * NK * NK];     // (W - 1/64)^T *16384 fp16 [n][o][i] 8 MB
static __device__ __half g_XLh[(size_t)NB * NN * NK];    // x_local fp16 [b][n][k] 32 MB
static __device__ __half g_Yh[(size_t)NB * NK * NN];     // Y fp16 [r][m] 32 MB
static __device__ __half g_STh[NN * NN];                 // (A - 1/1024)^T * 4096, fp16 [n][m] 2 MB
static __device__ float g_SY[NB * NK];                   // per-row sums of Y (exact fp32)

// ============================ PTX helpers (sm_80-era only!) ============================
__device__ __forceinline__ uint32_t smem_u32(const void* p) {
    uint32_t a;
    asm("{ .reg .u64 t; cvta.to.shared.u64 t, %1; cvt.u32.u64 %0, t; }" : "=r"(a) : "l"(p));
    return a;
}
__device__ __forceinline__ void cpa16(uint32_t s, const void* g) {
    asm volatile("cp.async.cg.shared.global [%0], [%1], 16;" :: "r"(s), "l"(g));
}
__device__ __forceinline__ void ldm4(uint32_t* r, uint32_t a) {
    asm volatile("ldmatrix.sync.aligned.m8n8.x4.shared.b16 {%0,%1,%2,%3}, [%4];"
                 : "=r"(r[0]), "=r"(r[1]), "=r"(r[2]), "=r"(r[3]) : "r"(a));
}
__device__ __forceinline__ void mma_fp16(float* d, const uint32_t* a, const uint32_t* b) {
    asm volatile(
        "mma.sync.aligned.m16n8k16.row.col.f32.f16.f16.f32 "
        "{%0,%1,%2,%3}, {%4,%5,%6,%7}, {%8,%9}, {%0,%1,%2,%3};"
        : "+f"(d[0]), "+f"(d[1]), "+f"(d[2]), "+f"(d[3])
        : "r"(a[0]), "r"(a[1]), "r"(a[2]), "r"(a[3]), "r"(b[0]), "r"(b[1]));
}

// ---------------------------------------------------------------------------
// Kernel 1: row pass. P[row] = exp(logits/T) / rowsum — linear domain, __expf.
// ---------------------------------------------------------------------------
__global__ void k_sink_row(const float* __restrict__ logits) {
    const int row = blockIdx.x;
    const int t = threadIdx.x;
    const float* rp = logits + (size_t)row * NN;
    float e[4];
    float acc = 0.f;
#pragma unroll
    for (int q = 0; q < 4; ++q) {
        e[q] = __expf(rp[t + 256 * q] * INV_TEMP);
        acc += e[q];
    }
    __shared__ float red[256];
    red[t] = acc;
    __syncthreads();
    for (int s = 128; s > 0; s >>= 1) {
        if (t < s) red[t] += red[t + s];
        __syncthreads();
    }
    const float rinv = 1.0f / red[0];
    float* op = g_S + (size_t)row * NN;
#pragma unroll
    for (int q = 0; q < 4; ++q) op[t + 256 * q] = e[q] * rinv;
}

// ---------------------------------------------------------------------------
// Kernel 2: column normalize + emit STh[n][m] = (P[m][n]/colsum - 1/1024)*4096
// directly (transposed, fp16) via a 135 KB smem buffer. No exp at all.
// ---------------------------------------------------------------------------
#define CP 33
__global__ void __launch_bounds__(256) k_sink_colT() {
    extern __shared__ float buf[];  // [1024][CP]
    const int c0 = blockIdx.x * 32;
    const int t = threadIdx.x;
    const int c = t & 31, ry = t >> 5;
    float csum = 0.f;
    for (int m = ry; m < NN; m += 8) {
        float v = g_S[(size_t)m * NN + c0 + c];
        buf[m * CP + c] = v;
        csum += v;
    }
    __shared__ float ss[8][32];
    __shared__ float cinv[32];
    ss[ry][c] = csum;
    __syncthreads();
    if (t < 32) {
        float S = 0.f;
#pragma unroll
        for (int q = 0; q < 8; ++q) S += ss[q][t];
        cinv[t] = 1.0f / S;
    }
    __syncthreads();
    const int w = t >> 5, L = t & 31;
#pragma unroll
    for (int j = 0; j < 4; ++j) {
        const int cc = w * 4 + j;
        const float ci = cinv[cc] * A_SCALE;  // STh = P*ci - 4  (A_SCALE/1024 = 4)
        __half2* op = (__half2*)(g_STh + (size_t)(c0 + cc) * NN);
#pragma unroll
        for (int q = 0; q < 16; ++q) {
            const int m = 2 * L + 64 * q;
            float a = buf[m * CP + cc] * ci - 4.0f;
            float b = buf[(m + 1) * CP + cc] * ci - 4.0f;
            op[m >> 1] = __floats2half2_rn(a, b);
        }
    }
}

// ---------------------------------------------------------------------------
// Kernel 3: per-block sinkhorn of W1.W_V, linear domain (__expf once, 2 rcps).
// Emits W'^T = (W - 1/64)*WP_SCALE fp16 [n][o][i].
// ---------------------------------------------------------------------------
__global__ void k_wsink(const float* __restrict__ W1, const float* __restrict__ WV) {
    const int n = blockIdx.x;
    const int t = threadIdx.x;
    __shared__ float L[64][65];
    __shared__ float w1[8];
    __shared__ float rinv[64], cinv[64];
    __shared__ float redc[4][64];
    if (t < 8) w1[t] = W1[n * 8 + t];
    __syncthreads();
#pragma unroll
    for (int q = 0; q < 16; ++q) {
        int idx = t + 256 * q;
        float acc = 0.f;
#pragma unroll
        for (int k = 0; k < 8; ++k) acc += w1[k] * WV[k * 4096 + idx];
        L[idx >> 6][idx & 63] = __expf(acc * INV_TEMP);
    }
    __syncthreads();
    {
        const int r = t >> 2, j0 = (t & 3) * 16;
        float s = 0.f;
#pragma unroll
        for (int e = 0; e < 16; ++e) s += L[r][j0 + e];
        s += __shfl_xor_sync(0xffffffffu, s, 1);
        s += __shfl_xor_sync(0xffffffffu, s, 2);
        if ((t & 3) == 0) rinv[r] = 1.0f / s;
    }
    __syncthreads();
    {
        const int o = t & 63, p = t >> 6;
        float cs = 0.f;
#pragma unroll
        for (int e = 0; e < 16; ++e) {
            const int d = p * 16 + e;
            float f = L[d][o] * rinv[d];
            L[d][o] = f;
            cs += f;
        }
        redc[p][o] = cs;
    }
    __syncthreads();
    if (t < 64)
        cinv[t] = 1.0f / ((redc[0][t] + redc[1][t]) + (redc[2][t] + redc[3][t]));
    __syncthreads();
    __half* wt = g_WT + (size_t)n * 4096;
#pragma unroll
    for (int q = 0; q < 16; ++q) {
        int idx = t + 256 * q;
        int o = idx >> 6, d = idx & 63;
        wt[idx] = __float2half((L[d][o] * cinv[o] - C_K) * WP_SCALE);
    }
}

// ---------------------------------------------------------------------------
// Kernel 4: x_local = sx/64 + (x@W'^T)/16384 via fp16 MMA. One n per block;
// loops over 4 b-chunks of 64 with double-buffered cp.async x staging so
// global latency overlaps MMA. WT loaded once per block.
// smem: Xf[2][64*68] fp32 | Xs[64*72] fp16 | Ws[64*72] fp16 | sxs[64] (dyn)
// ---------------------------------------------------------------------------
#define XF_SZ (64 * 68)
#define XL_SMEM (2 * XF_SZ * 4 + 64 * 72 * 2 * 2 + 64 * 4)
__global__ void __launch_bounds__(256) k_xlocal(const float* __restrict__ x) {
    extern __shared__ char dsm[];
    float* Xf0 = (float*)dsm;
    float* Xf1 = Xf0 + XF_SZ;
    __half* Xs = (__half*)(dsm + 2 * XF_SZ * 4);
    __half* Ws = Xs + 64 * 72;
    float* sxs = (float*)(Ws + 64 * 72);

    const int n = blockIdx.x;
    const int t = threadIdx.x;
    const int L = t & 31, w = t >> 5;

    // WT tile once per block
    {
        const __half* wp = g_WT + (size_t)n * 4096;
#pragma unroll
        for (int q = 0; q < 2; ++q) {
            int u = t + 256 * q;
            int row = u >> 3, c8 = (u & 7) * 8;
            *(uint4*)(Ws + row * 72 + c8) = *(const uint4*)(wp + u * 8);
        }
    }

    const uint32_t xf_s[2] = {smem_u32(Xf0), smem_u32(Xf1)};
    // Prefetch chunk 0
#pragma unroll
    for (int i = t; i < 1024; i += 256) {
        int row = i >> 4, q = i & 15;
        cpa16(xf_s[0] + (uint32_t)(row * 68 + q * 4) * 4,
              x + (size_t)row * (NN * NK) + n * NK + q * 4);
    }
    asm volatile("cp.async.commit_group;" ::: "memory");

    const int m0 = (w >> 1) * 16;
    const int wn = (w & 1) * 32;
    const uint32_t xb = smem_u32(Xs), wb = smem_u32(Ws);
    const uint32_t a_l = xb + (uint32_t)((m0 + (L & 15)) * 144 + (L >> 4) * 16);
    const uint32_t b_l = wb + (uint32_t)((wn + (L & 7) + ((L & 16) ? 8 : 0)) * 144 +
                                         ((L & 8) ? 16 : 0));
    const int crow = t >> 2, cc0 = (t & 3) * 16;

#pragma unroll 1
    for (int cb = 0; cb < 4; ++cb) {
        if (cb < 3) {
            const size_t gbase = (size_t)(cb + 1) * 64 * (NN * NK);
#pragma unroll
            for (int i = t; i < 1024; i += 256) {
                int row = i >> 4, q = i & 15;
                cpa16(xf_s[(cb + 1) & 1] + (uint32_t)(row * 68 + q * 4) * 4,
                      x + gbase + (size_t)row * (NN * NK) + n * NK + q * 4);
            }
            asm volatile("cp.async.commit_group;" ::: "memory");
            asm volatile("cp.async.wait_group 1;" ::: "memory");
        } else {
            asm volatile("cp.async.wait_group 0;" ::: "memory");
        }
        __syncthreads();

        // convert fp32 smem -> fp16 Xs + exact row sums
        {
            const float* xf = (cb & 1 ? Xf1 : Xf0) + crow * 68 + cc0;
            float4 v0 = *(const float4*)(xf + 0);
            float4 v1 = *(const float4*)(xf + 4);
            float4 v2 = *(const float4*)(xf + 8);
            float4 v3 = *(const float4*)(xf + 12);
            float s = ((v0.x + v0.y) + (v0.z + v0.w)) + ((v1.x + v1.y) + (v1.z + v1.w)) +
                      ((v2.x + v2.y) + (v2.z + v2.w)) + ((v3.x + v3.y) + (v3.z + v3.w));
            __half2* xs = (__half2*)(Xs + crow * 72 + cc0);
            xs[0] = __floats2half2_rn(v0.x, v0.y);
            xs[1] = __floats2half2_rn(v0.z, v0.w);
            xs[2] = __floats2half2_rn(v1.x, v1.y);
            xs[3] = __floats2half2_rn(v1.z, v1.w);
            xs[4] = __floats2half2_rn(v2.x, v2.y);
            xs[5] = __floats2half2_rn(v2.z, v2.w);
            xs[6] = __floats2half2_rn(v3.x, v3.y);
            xs[7] = __floats2half2_rn(v3.z, v3.w);
            s += __shfl_xor_sync(0xffffffffu, s, 1);
            s += __shfl_xor_sync(0xffffffffu, s, 2);
            if ((t & 3) == 0) sxs[crow] = s;
        }
        __syncthreads();

        float acc[4][4] = {};
#pragma unroll
        for (int ks = 0; ks < 4; ++ks) {
            uint32_t ar[4], br[2][4];
            ldm4(ar, a_l + ks * 32);
            ldm4(br[0], b_l + ks * 32);
            ldm4(br[1], b_l + ks * 32 + 16 * 144);
#pragma unroll
            for (int nj = 0; nj < 4; ++nj)
                mma_fp16(acc[nj], ar, &br[nj >> 1][(nj & 1) * 2]);
        }

        const int b0 = cb * 64;
        const int r = L >> 2;
        const float sx0 = sxs[m0 + r] * C_K, sx1 = sxs[m0 + r + 8] * C_K;
        __half* xl0 = g_XLh + ((size_t)(b0 + m0 + r) * NN + n) * NK;
        __half* xl1 = xl0 + (size_t)8 * NN * NK;
#pragma unroll
        for (int nj = 0; nj < 4; ++nj) {
            const int k = wn + nj * 8 + (L & 3) * 2;
            *(__half2*)(xl0 + k) =
                __floats2half2_rn(acc[nj][0] * WP_INV + sx0, acc[nj][1] * WP_INV + sx0);
            *(__half2*)(xl1 + k) =
                __floats2half2_rn(acc[nj][2] * WP_INV + sx1, acc[nj][3] * WP_INV + sx1);
        }
        __syncthreads();  // protect Xs/sxs before next chunk's convert
    }
}

// ---------------------------------------------------------------------------
// Kernel 5: layernorm over n (per (b,k)) + transpose, k-chunk 8 (33 KB smem,
// 6 blocks/SM). Reads fp16 XL, emits fp16 Y [r][m] + exact fp32 row sums.
// ---------------------------------------------------------------------------
#define LBUF 1025
__global__ void __launch_bounds__(256) k_lnt(const float* __restrict__ gamma2,
                                             const float* __restrict__ beta2) {
    extern __shared__ float buf[];  // [8][LBUF]
    const int b = blockIdx.x;
    const int k0 = blockIdx.y * 8;
    const int t = threadIdx.x;
    const __half* base = g_XLh + (size_t)b * NN * NK + k0;
    // Load [1024 n][8 k] fp16 (one uint4 per n-row), transpose to buf[k][n]
#pragma unroll
    for (int q = 0; q < 4; ++q) {
        const int nn = t + 256 * q;
        uint4 v = *(const uint4*)(base + (size_t)nn * NK);
        const __half2* h = (const __half2*)&v;
#pragma unroll
        for (int j = 0; j < 4; ++j) {
            float2 f = __half22float2(h[j]);
            buf[(2 * j) * LBUF + nn] = f.x;
            buf[(2 * j + 1) * LBUF + nn] = f.y;
        }
    }
    __syncthreads();
    __shared__ float ps[32][9], ps2[32][9], mu[8], rs[8];
    {
        const int kc = t & 7, nr = t >> 3;
        float s = 0.f, s2 = 0.f;
        for (int nn = nr; nn < NN; nn += 32) {
            float v = buf[kc * LBUF + nn];
            s += v;
            s2 += v * v;
        }
        ps[nr][kc] = s;
        ps2[nr][kc] = s2;
    }
    __syncthreads();
    if (t < 8) {
        float S = 0.f, S2 = 0.f;
#pragma unroll
        for (int q = 0; q < 32; ++q) { S += ps[q][t]; S2 += ps2[q][t]; }
        float m = S * (1.0f / NN);
        mu[t] = m;
        rs[t] = rsqrtf(S2 * (1.0f / NN) - m * m + LN_EPS);
    }
    __syncthreads();
    const int L = t & 31, w = t >> 5;
    const float m = mu[w], r = rs[w];
    __half2* yp = (__half2*)(g_Yh + (size_t)(b * NK + k0 + w) * NN);
    float sy = 0.f;
#pragma unroll
    for (int q = 0; q < 16; ++q) {
        const int nn = 2 * L + 64 * q;
        float2 g = *(const float2*)(gamma2 + nn);
        float2 bt = *(const float2*)(beta2 + nn);
        float v0 = (buf[w * LBUF + nn] - m) * r * g.x + bt.x;
        float v1 = (buf[w * LBUF + nn + 1] - m) * r * g.y + bt.y;
        sy += v0 + v1;
        yp[nn >> 1] = __floats2half2_rn(v0, v1);
    }
#pragma unroll
    for (int off = 16; off; off >>= 1) sy += __shfl_xor_sync(0xffffffffu, sy, off);
    if (L == 0) g_SY[b * NK + k0 + w] = sy;
}

// ---------------------------------------------------------------------------
// Kernel 6: single-pass fp16 tensor-core GEMM, 3-stage cp.async pipeline.
//   D[r][n] = sum_m Yh[r][m] * STh[n][m];  out = D/A_SCALE + SY[r]/1024.
// ---------------------------------------------------------------------------
#define T_ROWB 144
#define TILE_B (128 * T_ROWB)
#define STAGE_B (2 * TILE_B)
#define OFF_Y 0u
#define OFF_S ((uint32_t)TILE_B)

__device__ __forceinline__ void g_load_stage(uint32_t st, int r0, int n0, int m0, int t) {
    for (int i = t; i < 1024; i += 256) {
        const int row = i >> 3, q = i & 7;
        const uint32_t so = (uint32_t)(row * T_ROWB + q * 16);
        cpa16(st + OFF_Y + so, g_Yh + (size_t)(r0 + row) * NN + m0 + q * 8);
        cpa16(st + OFF_S + so, g_STh + (size_t)(n0 + row) * NN + m0 + q * 8);
    }
}

__global__ void __launch_bounds__(256) k_gemm_mma(float* __restrict__ out) {
    extern __shared__ char dsm[];
    const int t = threadIdx.x;
    const int r0 = blockIdx.x * 128;
    const int n0 = blockIdx.y * 128;
    __shared__ float s_sy[128];
    if (t < 128) s_sy[t] = g_SY[r0 + t] * C_N;
    const uint32_t sb = smem_u32(dsm);

    g_load_stage(sb, r0, n0, 0, t);
    asm volatile("cp.async.commit_group;" ::: "memory");
    g_load_stage(sb + STAGE_B, r0, n0, 64, t);
    asm volatile("cp.async.commit_group;" ::: "memory");
    g_load_stage(sb + 2 * STAGE_B, r0, n0, 128, t);
    asm volatile("cp.async.commit_group;" ::: "memory");

    const int L = t & 31, w = t >> 5;
    const int wr = (w >> 1) * 32;
    const int wn = (w & 1) * 64;
    const uint32_t a_l = (uint32_t)((wr + (L & 15)) * T_ROWB + ((L >> 4) * 8) * 2);
    const uint32_t b_l = (uint32_t)((wn + (L & 7) + ((L & 16) ? 8 : 0)) * T_ROWB + ((L & 8) ? 16 : 0));

    float acc[2][8][4] = {};
    int stg = 0;

#pragma unroll 1
    for (int c = 0; c < 16; ++c) {
        if (c < 14)       asm volatile("cp.async.wait_group 2;" ::: "memory");
        else if (c == 14) asm volatile("cp.async.wait_group 1;" ::: "memory");
        else              asm volatile("cp.async.wait_group 0;" ::: "memory");
        __syncthreads();
        const uint32_t st = sb + (uint32_t)stg * STAGE_B;
#pragma unroll
        for (int ks = 0; ks < 4; ++ks) {
            uint32_t ah[2][4], bh[4][4];
            const uint32_t ka = st + a_l + ks * 32;
            const uint32_t kb = st + b_l + ks * 32;
#pragma unroll
            for (int mt = 0; mt < 2; ++mt)
                ldm4(ah[mt], ka + OFF_Y + mt * (16 * T_ROWB));
#pragma unroll
            for (int bj = 0; bj < 4; ++bj)
                ldm4(bh[bj], kb + OFF_S + bj * (16 * T_ROWB));
#pragma unroll
            for (int mt = 0; mt < 2; ++mt)
#pragma unroll
                for (int nj = 0; nj < 8; ++nj)
                    mma_fp16(acc[mt][nj], ah[mt], &bh[nj >> 1][(nj & 1) * 2]);
        }
        __syncthreads();
        if (c + 3 < 16) {
            g_load_stage(st, r0, n0, (c + 3) * 64, t);
            asm volatile("cp.async.commit_group;" ::: "memory");
        }
        stg = (stg == 2) ? 0 : stg + 1;
    }

    // Epilogue: acc -> smem [n][r], then coalesced float4 STG.
    float* so = (float*)dsm;
#pragma unroll
    for (int mt = 0; mt < 2; ++mt)
#pragma unroll
        for (int nj = 0; nj < 8; ++nj) {
            const int rl = wr + mt * 16 + (L >> 2);
            const int nl = wn + nj * 8 + (L & 3) * 2;
            so[nl * 132 + rl]           = acc[mt][nj][0];
            so[(nl + 1) * 132 + rl]     = acc[mt][nj][1];
            so[nl * 132 + rl + 8]       = acc[mt][nj][2];
            so[(nl + 1) * 132 + rl + 8] = acc[mt][nj][3];
        }
    __syncthreads();
    for (int i = t; i < 4096; i += 256) {
        const int n = i >> 5;
        const int rq = (i & 31) * 4;
        float4 v;
        v.x = so[n * 132 + rq]     * A_INV_SCALE + s_sy[rq];
        v.y = so[n * 132 + rq + 1] * A_INV_SCALE + s_sy[rq + 1];
        v.z = so[n * 132 + rq + 2] * A_INV_SCALE + s_sy[rq + 2];
        v.w = so[n * 132 + rq + 3] * A_INV_SCALE + s_sy[rq + 3];
        const int r = r0 + rq;
        *(float4*)(out + (size_t)(r >> 6) * (NN * NK) + (size_t)(n0 + n) * NK + (r & 63)) = v;
    }
}

// ---------------------------------------------------------------------------
extern "C" void kernel_launch(void* const* d_in, const int* in_sizes, int n_in,
                              void* d_out, int out_size) {
    (void)in_sizes; (void)n_in; (void)out_size;
    const float* x        = (const float*)d_in[0];  // [B, N*K]
    const float* A_logits = (const float*)d_in[1];  // [N, N]
    const float* W1       = (const float*)d_in[2];  // [N, 8]
    const float* WV       = (const float*)d_in[3];  // [8, K, K]
    const float* gamma2   = (const float*)d_in[4];  // [N]
    const float* beta2    = (const float*)d_in[5];  // [N]
    float* out = (float*)d_out;

    static int smem_set = 0;
    if (!smem_set) {
        cudaFuncSetAttribute(k_gemm_mma, cudaFuncAttributeMaxDynamicSharedMemorySize,
                             3 * STAGE_B);
        cudaFuncSetAttribute(k_lnt, cudaFuncAttributeMaxDynamicSharedMemorySize,
                             8 * LBUF * 4);
        cudaFuncSetAttribute(k_sink_colT, cudaFuncAttributeMaxDynamicSharedMemorySize,
                             NN * CP * 4);
        cudaFuncSetAttribute(k_xlocal, cudaFuncAttributeMaxDynamicSharedMemorySize,
                             XL_SMEM);
        smem_set = 1;
    }

    k_sink_row<<<NN, 256>>>(A_logits);
    k_sink_colT<<<32, 256, NN * CP * 4>>>();
    k_wsink<<<NN, 256>>>(W1, WV);
    k_xlocal<<<NN, 256, XL_SMEM>>>(x);
    k_lnt<<<dim3(NB, 8), 256, 8 * LBUF * 4>>>(gamma2, beta2);
    k_gemm_mma<<<dim3(128, 8), 256, 3 * STAGE_B>>>(out);
}

// round 15
// speedup vs baseline: 3.8481x; 1.0017x over previous
#include <cuda_runtime.h>
#include <cuda_bf16.h>
#include <cuda_fp16.h>
#include <math.h>
#include <stdint.h>

// Problem constants
#define NB 256        // batch B
#define NN 1024       // N
#define NK 64         // K
#define INV_TEMP 5.0f // 1/0.2
#define LN_EPS 1e-5f
#define A_SCALE 4096.0f
#define A_INV_SCALE 2.44140625e-4f
#define WP_SCALE 16384.0f
#define WP_INV (1.0f / 16384.0f)
#define C_N 9.765625e-4f   // 1/1024 exact
#define C_K 0.015625f      // 1/64 exact

// Scratch (static device globals; allocation inside kernel_launch is forbidden)
static __device__ float g_S[NN * NN];                    // row-stochastic P 4 MB
static __device__ __half g_WT[(size_t)NN * NK * NK];     // (W - 1/64)^T *16384 fp16 [n][o][i] 8 MB
static __device__ __half g_XLh[(size_t)NB * NN * NK];    // x_local fp16 [b][n][k] 32 MB
static __device__ __half g_Yh[(size_t)NB * NK * NN];     // Y fp16 [r][m] 32 MB
static __device__ __half g_STh[NN * NN];                 // (A - 1/1024)^T * 4096, fp16 [n][m] 2 MB
static __device__ float g_SY[NB * NK];                   // per-row sums of Y (exact fp32)

// ============================ PTX helpers (sm_80-era only!) ============================
__device__ __forceinline__ uint32_t smem_u32(const void* p) {
    uint32_t a;
    asm("{ .reg .u64 t; cvta.to.shared.u64 t, %1; cvt.u32.u64 %0, t; }" : "=r"(a) : "l"(p));
    return a;
}
__device__ __forceinline__ void cpa16(uint32_t s, const void* g) {
    asm volatile("cp.async.cg.shared.global [%0], [%1], 16;" :: "r"(s), "l"(g));
}
__device__ __forceinline__ void ldm4(uint32_t* r, uint32_t a) {
    asm volatile("ldmatrix.sync.aligned.m8n8.x4.shared.b16 {%0,%1,%2,%3}, [%4];"
                 : "=r"(r[0]), "=r"(r[1]), "=r"(r[2]), "=r"(r[3]) : "r"(a));
}
__device__ __forceinline__ void mma_fp16(float* d, const uint32_t* a, const uint32_t* b) {
    asm volatile(
        "mma.sync.aligned.m16n8k16.row.col.f32.f16.f16.f32 "
        "{%0,%1,%2,%3}, {%4,%5,%6,%7}, {%8,%9}, {%0,%1,%2,%3};"
        : "+f"(d[0]), "+f"(d[1]), "+f"(d[2]), "+f"(d[3])
        : "r"(a[0]), "r"(a[1]), "r"(a[2]), "r"(a[3]), "r"(b[0]), "r"(b[1]));
}

// ---------------------------------------------------------------------------
// Kernel 1: row pass. P[row] = exp(logits/T) / rowsum — linear domain, __expf.
// ---------------------------------------------------------------------------
__global__ void k_sink_row(const float* __restrict__ logits) {
    const int row = blockIdx.x;
    const int t = threadIdx.x;
    const float* rp = logits + (size_t)row * NN;
    float e[4];
    float acc = 0.f;
#pragma unroll
    for (int q = 0; q < 4; ++q) {
        e[q] = __expf(rp[t + 256 * q] * INV_TEMP);
        acc += e[q];
    }
    __shared__ float red[256];
    red[t] = acc;
    __syncthreads();
    for (int s = 128; s > 0; s >>= 1) {
        if (t < s) red[t] += red[t + s];
        __syncthreads();
    }
    const float rinv = 1.0f / red[0];
    float* op = g_S + (size_t)row * NN;
#pragma unroll
    for (int q = 0; q < 4; ++q) op[t + 256 * q] = e[q] * rinv;
}

// ---------------------------------------------------------------------------
// Kernel 2: column normalize + emit STh[n][m] = (P[m][n]/colsum - 1/1024)*4096
// directly (transposed, fp16) via a 135 KB smem buffer. No exp at all.
// ---------------------------------------------------------------------------
#define CP 33
__global__ void __launch_bounds__(256) k_sink_colT() {
    extern __shared__ float buf[];  // [1024][CP]
    const int c0 = blockIdx.x * 32;
    const int t = threadIdx.x;
    const int c = t & 31, ry = t >> 5;
    float csum = 0.f;
    for (int m = ry; m < NN; m += 8) {
        float v = g_S[(size_t)m * NN + c0 + c];
        buf[m * CP + c] = v;
        csum += v;
    }
    __shared__ float ss[8][32];
    __shared__ float cinv[32];
    ss[ry][c] = csum;
    __syncthreads();
    if (t < 32) {
        float S = 0.f;
#pragma unroll
        for (int q = 0; q < 8; ++q) S += ss[q][t];
        cinv[t] = 1.0f / S;
    }
    __syncthreads();
    const int w = t >> 5, L = t & 31;
#pragma unroll
    for (int j = 0; j < 4; ++j) {
        const int cc = w * 4 + j;
        const float ci = cinv[cc] * A_SCALE;  // STh = P*ci - 4  (A_SCALE/1024 = 4)
        __half2* op = (__half2*)(g_STh + (size_t)(c0 + cc) * NN);
#pragma unroll
        for (int q = 0; q < 16; ++q) {
            const int m = 2 * L + 64 * q;
            float a = buf[m * CP + cc] * ci - 4.0f;
            float b = buf[(m + 1) * CP + cc] * ci - 4.0f;
            op[m >> 1] = __floats2half2_rn(a, b);
        }
    }
}

// ---------------------------------------------------------------------------
// Kernel 3: per-block sinkhorn of W1.W_V, linear domain (__expf once, 2 rcps).
// Emits W'^T = (W - 1/64)*WP_SCALE fp16 [n][o][i].
// ---------------------------------------------------------------------------
__global__ void k_wsink(const float* __restrict__ W1, const float* __restrict__ WV) {
    const int n = blockIdx.x;
    const int t = threadIdx.x;
    __shared__ float L[64][65];
    __shared__ float w1[8];
    __shared__ float rinv[64], cinv[64];
    __shared__ float redc[4][64];
    if (t < 8) w1[t] = W1[n * 8 + t];
    __syncthreads();
#pragma unroll
    for (int q = 0; q < 16; ++q) {
        int idx = t + 256 * q;
        float acc = 0.f;
#pragma unroll
        for (int k = 0; k < 8; ++k) acc += w1[k] * WV[k * 4096 + idx];
        L[idx >> 6][idx & 63] = __expf(acc * INV_TEMP);
    }
    __syncthreads();
    {
        const int r = t >> 2, j0 = (t & 3) * 16;
        float s = 0.f;
#pragma unroll
        for (int e = 0; e < 16; ++e) s += L[r][j0 + e];
        s += __shfl_xor_sync(0xffffffffu, s, 1);
        s += __shfl_xor_sync(0xffffffffu, s, 2);
        if ((t & 3) == 0) rinv[r] = 1.0f / s;
    }
    __syncthreads();
    {
        const int o = t & 63, p = t >> 6;
        float cs = 0.f;
#pragma unroll
        for (int e = 0; e < 16; ++e) {
            const int d = p * 16 + e;
            float f = L[d][o] * rinv[d];
            L[d][o] = f;
            cs += f;
        }
        redc[p][o] = cs;
    }
    __syncthreads();
    if (t < 64)
        cinv[t] = 1.0f / ((redc[0][t] + redc[1][t]) + (redc[2][t] + redc[3][t]));
    __syncthreads();
    __half* wt = g_WT + (size_t)n * 4096;
#pragma unroll
    for (int q = 0; q < 16; ++q) {
        int idx = t + 256 * q;
        int o = idx >> 6, d = idx & 63;
        wt[idx] = __float2half((L[d][o] * cinv[o] - C_K) * WP_SCALE);
    }
}

// ---------------------------------------------------------------------------
// Kernel 4: x_local = sx/64 + (x@W'^T)/16384 via fp16 MMA. One n per block,
// ALL 256 b rows in one pass: every global load issued before the single
// sync (MLP ~16/thread), so DRAM latency is paid once per block. 8 warps,
// warp tile 32(b) x 64(k).
// smem: Xs fp16 [256][72] | Ws fp16 [64][72] | sxs[256] fp32  (= 47104 B)
// ---------------------------------------------------------------------------
#define XL_SMEM (256 * 72 * 2 + 64 * 72 * 2 + 256 * 4)
__global__ void __launch_bounds__(256) k_xlocal(const float* __restrict__ x) {
    extern __shared__ char dsm[];
    __half* Xs = (__half*)dsm;                 // [256][72]
    __half* Ws = Xs + 256 * 72;                // [64][72]
    float* sxs = (float*)(Ws + 64 * 72);       // [256]

    const int n = blockIdx.x;
    const int t = threadIdx.x;
    const int L = t & 31, w = t >> 5;

    // WT tile once per block
    {
        const __half* wp = g_WT + (size_t)n * 4096;
#pragma unroll
        for (int q = 0; q < 2; ++q) {
            int u = t + 256 * q;
            int row = u >> 3, c8 = (u & 7) * 8;
            *(uint4*)(Ws + row * 72 + c8) = *(const uint4*)(wp + u * 8);
        }
    }

    // X: 4 threads per row, 4 row-passes — 16 independent LDG.128 per thread.
    {
        const int rbase = t >> 2, c0 = (t & 3) * 16;
#pragma unroll
        for (int q = 0; q < 4; ++q) {
            const int row = rbase + 64 * q;
            const float* xp = x + (size_t)row * (NN * NK) + n * NK + c0;
            float4 v0 = *(const float4*)(xp + 0);
            float4 v1 = *(const float4*)(xp + 4);
            float4 v2 = *(const float4*)(xp + 8);
            float4 v3 = *(const float4*)(xp + 12);
            float s = ((v0.x + v0.y) + (v0.z + v0.w)) + ((v1.x + v1.y) + (v1.z + v1.w)) +
                      ((v2.x + v2.y) + (v2.z + v2.w)) + ((v3.x + v3.y) + (v3.z + v3.w));
            __half2* xs = (__half2*)(Xs + row * 72 + c0);
            xs[0] = __floats2half2_rn(v0.x, v0.y);
            xs[1] = __floats2half2_rn(v0.z, v0.w);
            xs[2] = __floats2half2_rn(v1.x, v1.y);
            xs[3] = __floats2half2_rn(v1.z, v1.w);
            xs[4] = __floats2half2_rn(v2.x, v2.y);
            xs[5] = __floats2half2_rn(v2.z, v2.w);
            xs[6] = __floats2half2_rn(v3.x, v3.y);
            xs[7] = __floats2half2_rn(v3.z, v3.w);
            s += __shfl_xor_sync(0xffffffffu, s, 1);
            s += __shfl_xor_sync(0xffffffffu, s, 2);
            if ((t & 3) == 0) sxs[row] = s;
        }
    }
    __syncthreads();

    // MMA: warp w owns b rows [w*32, w*32+32), all 64 k.
    const int m0 = w * 32;
    const uint32_t xb = smem_u32(Xs), wb = smem_u32(Ws);
    const uint32_t a_l = xb + (uint32_t)((m0 + (L & 15)) * 144 + (L >> 4) * 16);
    const uint32_t b_l = wb + (uint32_t)(((L & 7) + ((L & 16) ? 8 : 0)) * 144 +
                                         ((L & 8) ? 16 : 0));
    float acc[2][8][4] = {};
#pragma unroll
    for (int ks = 0; ks < 4; ++ks) {
        uint32_t ah[2][4], bh[4][4];
#pragma unroll
        for (int mt = 0; mt < 2; ++mt)
            ldm4(ah[mt], a_l + ks * 32 + mt * (16 * 144));
#pragma unroll
        for (int bj = 0; bj < 4; ++bj)
            ldm4(bh[bj], b_l + ks * 32 + bj * (16 * 144));
#pragma unroll
        for (int mt = 0; mt < 2; ++mt)
#pragma unroll
            for (int nj = 0; nj < 8; ++nj)
                mma_fp16(acc[mt][nj], ah[mt], &bh[nj >> 1][(nj & 1) * 2]);
    }

    // Epilogue: xl = acc*WP_INV + sx/64, fp16 [b][n][k]
    const int r = L >> 2;
#pragma unroll
    for (int mt = 0; mt < 2; ++mt) {
        const int b0 = m0 + mt * 16 + r;
        const float sx0 = sxs[b0] * C_K, sx1 = sxs[b0 + 8] * C_K;
        __half* xl0 = g_XLh + ((size_t)b0 * NN + n) * NK;
        __half* xl1 = xl0 + (size_t)8 * NN * NK;
#pragma unroll
        for (int nj = 0; nj < 8; ++nj) {
            const int k = nj * 8 + (L & 3) * 2;
            *(__half2*)(xl0 + k) =
                __floats2half2_rn(acc[mt][nj][0] * WP_INV + sx0, acc[mt][nj][1] * WP_INV + sx0);
            *(__half2*)(xl1 + k) =
                __floats2half2_rn(acc[mt][nj][2] * WP_INV + sx1, acc[mt][nj][3] * WP_INV + sx1);
        }
    }
}

// ---------------------------------------------------------------------------
// Kernel 5: layernorm over n (per (b,k)) + transpose, k-chunk 8 (33 KB smem,
// 6 blocks/SM). Reads fp16 XL, emits fp16 Y [r][m] + exact fp32 row sums.
// ---------------------------------------------------------------------------
#define LBUF 1025
__global__ void __launch_bounds__(256) k_lnt(const float* __restrict__ gamma2,
                                             const float* __restrict__ beta2) {
    extern __shared__ float buf[];  // [8][LBUF]
    const int b = blockIdx.x;
    const int k0 = blockIdx.y * 8;
    const int t = threadIdx.x;
    const __half* base = g_XLh + (size_t)b * NN * NK + k0;
#pragma unroll
    for (int q = 0; q < 4; ++q) {
        const int nn = t + 256 * q;
        uint4 v = *(const uint4*)(base + (size_t)nn * NK);
        const __half2* h = (const __half2*)&v;
#pragma unroll
        for (int j = 0; j < 4; ++j) {
            float2 f = __half22float2(h[j]);
            buf[(2 * j) * LBUF + nn] = f.x;
            buf[(2 * j + 1) * LBUF + nn] = f.y;
        }
    }
    __syncthreads();
    __shared__ float ps[32][9], ps2[32][9], mu[8], rs[8];
    {
        const int kc = t & 7, nr = t >> 3;
        float s = 0.f, s2 = 0.f;
        for (int nn = nr; nn < NN; nn += 32) {
            float v = buf[kc * LBUF + nn];
            s += v;
            s2 += v * v;
        }
        ps[nr][kc] = s;
        ps2[nr][kc] = s2;
    }
    __syncthreads();
    if (t < 8) {
        float S = 0.f, S2 = 0.f;
#pragma unroll
        for (int q = 0; q < 32; ++q) { S += ps[q][t]; S2 += ps2[q][t]; }
        float m = S * (1.0f / NN);
        mu[t] = m;
        rs[t] = rsqrtf(S2 * (1.0f / NN) - m * m + LN_EPS);
    }
    __syncthreads();
    const int L = t & 31, w = t >> 5;
    const float m = mu[w], r = rs[w];
    __half2* yp = (__half2*)(g_Yh + (size_t)(b * NK + k0 + w) * NN);
    float sy = 0.f;
#pragma unroll
    for (int q = 0; q < 16; ++q) {
        const int nn = 2 * L + 64 * q;
        float2 g = *(const float2*)(gamma2 + nn);
        float2 bt = *(const float2*)(beta2 + nn);
        float v0 = (buf[w * LBUF + nn] - m) * r * g.x + bt.x;
        float v1 = (buf[w * LBUF + nn + 1] - m) * r * g.y + bt.y;
        sy += v0 + v1;
        yp[nn >> 1] = __floats2half2_rn(v0, v1);
    }
#pragma unroll
    for (int off = 16; off; off >>= 1) sy += __shfl_xor_sync(0xffffffffu, sy, off);
    if (L == 0) g_SY[b * NK + k0 + w] = sy;
}

// ---------------------------------------------------------------------------
// Kernel 6: single-pass fp16 tensor-core GEMM, 3-stage cp.async pipeline.
//   D[r][n] = sum_m Yh[r][m] * STh[n][m];  out = D/A_SCALE + SY[r]/1024.
// ---------------------------------------------------------------------------
#define T_ROWB 144
#define TILE_B (128 * T_ROWB)
#define STAGE_B (2 * TILE_B)
#define OFF_Y 0u
#define OFF_S ((uint32_t)TILE_B)

__device__ __forceinline__ void g_load_stage(uint32_t st, int r0, int n0, int m0, int t) {
    for (int i = t; i < 1024; i += 256) {
        const int row = i >> 3, q = i & 7;
        const uint32_t so = (uint32_t)(row * T_ROWB + q * 16);
        cpa16(st + OFF_Y + so, g_Yh + (size_t)(r0 + row) * NN + m0 + q * 8);
        cpa16(st + OFF_S + so, g_STh + (size_t)(n0 + row) * NN + m0 + q * 8);
    }
}

__global__ void __launch_bounds__(256) k_gemm_mma(float* __restrict__ out) {
    extern __shared__ char dsm[];
    const int t = threadIdx.x;
    const int r0 = blockIdx.x * 128;
    const int n0 = blockIdx.y * 128;
    __shared__ float s_sy[128];
    if (t < 128) s_sy[t] = g_SY[r0 + t] * C_N;
    const uint32_t sb = smem_u32(dsm);

    g_load_stage(sb, r0, n0, 0, t);
    asm volatile("cp.async.commit_group;" ::: "memory");
    g_load_stage(sb + STAGE_B, r0, n0, 64, t);
    asm volatile("cp.async.commit_group;" ::: "memory");
    g_load_stage(sb + 2 * STAGE_B, r0, n0, 128, t);
    asm volatile("cp.async.commit_group;" ::: "memory");

    const int L = t & 31, w = t >> 5;
    const int wr = (w >> 1) * 32;
    const int wn = (w & 1) * 64;
    const uint32_t a_l = (uint32_t)((wr + (L & 15)) * T_ROWB + ((L >> 4) * 8) * 2);
    const uint32_t b_l = (uint32_t)((wn + (L & 7) + ((L & 16) ? 8 : 0)) * T_ROWB + ((L & 8) ? 16 : 0));

    float acc[2][8][4] = {};
    int stg = 0;

#pragma unroll 1
    for (int c = 0; c < 16; ++c) {
        if (c < 14)       asm volatile("cp.async.wait_group 2;" ::: "memory");
        else if (c == 14) asm volatile("cp.async.wait_group 1;" ::: "memory");
        else              asm volatile("cp.async.wait_group 0;" ::: "memory");
        __syncthreads();
        const uint32_t st = sb + (uint32_t)stg * STAGE_B;
#pragma unroll
        for (int ks = 0; ks < 4; ++ks) {
            uint32_t ah[2][4], bh[4][4];
            const uint32_t ka = st + a_l + ks * 32;
            const uint32_t kb = st + b_l + ks * 32;
#pragma unroll
            for (int mt = 0; mt < 2; ++mt)
                ldm4(ah[mt], ka + OFF_Y + mt * (16 * T_ROWB));
#pragma unroll
            for (int bj = 0; bj < 4; ++bj)
                ldm4(bh[bj], kb + OFF_S + bj * (16 * T_ROWB));
#pragma unroll
            for (int mt = 0; mt < 2; ++mt)
#pragma unroll
                for (int nj = 0; nj < 8; ++nj)
                    mma_fp16(acc[mt][nj], ah[mt], &bh[nj >> 1][(nj & 1) * 2]);
        }
        __syncthreads();
        if (c + 3 < 16) {
            g_load_stage(st, r0, n0, (c + 3) * 64, t);
            asm volatile("cp.async.commit_group;" ::: "memory");
        }
        stg = (stg == 2) ? 0 : stg + 1;
    }

    // Epilogue: acc -> smem [n][r], then coalesced float4 STG.
    float* so = (float*)dsm;
#pragma unroll
    for (int mt = 0; mt < 2; ++mt)
#pragma unroll
        for (int nj = 0; nj < 8; ++nj) {
            const int rl = wr + mt * 16 + (L >> 2);
            const int nl = wn + nj * 8 + (L & 3) * 2;
            so[nl * 132 + rl]           = acc[mt][nj][0];
            so[(nl + 1) * 132 + rl]     = acc[mt][nj][1];
            so[nl * 132 + rl + 8]       = acc[mt][nj][2];
            so[(nl + 1) * 132 + rl + 8] = acc[mt][nj][3];
        }
    __syncthreads();
    for (int i = t; i < 4096; i += 256) {
        const int n = i >> 5;
        const int rq = (i & 31) * 4;
        float4 v;
        v.x = so[n * 132 + rq]     * A_INV_SCALE + s_sy[rq];
        v.y = so[n * 132 + rq + 1] * A_INV_SCALE + s_sy[rq + 1];
        v.z = so[n * 132 + rq + 2] * A_INV_SCALE + s_sy[rq + 2];
        v.w = so[n * 132 + rq + 3] * A_INV_SCALE + s_sy[rq + 3];
        const int r = r0 + rq;
        *(float4*)(out + (size_t)(r >> 6) * (NN * NK) + (size_t)(n0 + n) * NK + (r & 63)) = v;
    }
}

// ---------------------------------------------------------------------------
extern "C" void kernel_launch(void* const* d_in, const int* in_sizes, int n_in,
                              void* d_out, int out_size) {
    (void)in_sizes; (void)n_in; (void)out_size;
    const float* x        = (const float*)d_in[0];  // [B, N*K]
    const float* A_logits = (const float*)d_in[1];  // [N, N]
    const float* W1       = (const float*)d_in[2];  // [N, 8]
    const float* WV       = (const float*)d_in[3];  // [8, K, K]
    const float* gamma2   = (const float*)d_in[4];  // [N]
    const float* beta2    = (const float*)d_in[5];  // [N]
    float* out = (float*)d_out;

    static int smem_set = 0;
    if (!smem_set) {
        cudaFuncSetAttribute(k_gemm_mma, cudaFuncAttributeMaxDynamicSharedMemorySize,
                             3 * STAGE_B);
        cudaFuncSetAttribute(k_lnt, cudaFuncAttributeMaxDynamicSharedMemorySize,
                             8 * LBUF * 4);
        cudaFuncSetAttribute(k_sink_colT, cudaFuncAttributeMaxDynamicSharedMemorySize,
                             NN * CP * 4);
        cudaFuncSetAttribute(k_xlocal, cudaFuncAttributeMaxDynamicSharedMemorySize,
                             XL_SMEM);
        smem_set = 1;
    }

    k_sink_row<<<NN, 256>>>(A_logits);
    k_sink_colT<<<32, 256, NN * CP * 4>>>();
    k_wsink<<<NN, 256>>>(W1, WV);
    k_xlocal<<<NN, 256, XL_SMEM>>>(x);
    k_lnt<<<dim3(NB, 8), 256, 8 * LBUF * 4>>>(gamma2, beta2);
    k_gemm_mma<<<dim3(128, 8), 256, 3 * STAGE_B>>>(out);
}